// round 1
// baseline (speedup 1.0000x reference)
#include <cuda_runtime.h>
#include <math.h>

// ---------------- problem constants ----------------
static constexpr int Bx = 32, Lx = 680, Cx = 1024;
static constexpr int Sx = 10, SLOTSx = 32, Rx = 8, NCATx = 22;
static constexpr int MRx = 64, AHx = 128;
static constexpr int NROW = Bx * Lx;            // 21760
static constexpr int NKMAX = Sx * SLOTSx;       // 320
static constexpr int TQ = 16;

__constant__ int c_begin[10] = {0,1,5,14,30,55,91,155,255,424};
__constant__ int c_len[10]   = {1,4,9,16,25,36,64,100,169,256};
__constant__ int c_cumt[11]  = {0,1,2,3,4,6,9,13,20,31,47};   // ceil(len/16) cumulative

// ---------------- device scratch ----------------
__device__ float g_query[NROW * Cx];
__device__ float g_qh[NROW * AHx];
__device__ float g_sk[Sx * SLOTSx * Cx];
__device__ float g_sv[Sx * SLOTSx * Cx];
__device__ float g_cbk[Sx * Rx * SLOTSx * Cx];
__device__ float g_cbv[Sx * Rx * SLOTSx * Cx];
__device__ float g_kc[Bx * Sx * SLOTSx * Cx];
__device__ float g_vc[Bx * Sx * SLOTSx * Cx];
__device__ float g_acat[NCATx * AHx];
__device__ float g_ascale[Sx * AHx];
__device__ float g_mem[NROW * Cx];
__device__ float g_t1k[NROW * MRx];
__device__ float g_t1v[NROW * MRx];
__device__ float g_scal[4];   // [0]=logit scale, [1]=sig(gk), [2]=sig(gv)

// ---------------- prep ----------------
__global__ void prep_kernel(const float* gk, const float* gv, const float* lt) {
    float temp = expf(lt[0]);
    temp = fminf(fmaxf(temp, 0.05f), 1.0f);
    g_scal[0] = (1.0f / 32.0f) / temp;       // 1/sqrt(1024)/temp
    g_scal[1] = 1.0f / (1.0f + expf(-gk[0]));
    g_scal[2] = 1.0f / (1.0f + expf(-gv[0]));
}

// ---------------- generic fp32 SGEMM (128x128x8, 8x8 per thread) ----------------
__global__ void __launch_bounds__(256) sgemm_kernel(
    int M, int N, int K,
    const float* __restrict__ A, int lda,
    const float* __restrict__ B, int ldb,
    float* __restrict__ C, int ldc,
    const float* __restrict__ bias,
    const float* __restrict__ gate)
{
    constexpr int BM=128, BN=128, BK=8, TM=8, TN=8;
    __shared__ float As[BK][BM];
    __shared__ float Bs[BK][BN];
    int tid = threadIdx.x;
    int bm = blockIdx.y * BM;
    int bn = blockIdx.x * BN;
    int tx = tid & 15;
    int ty = tid >> 4;
    float acc[TM][TN];
    #pragma unroll
    for (int m=0;m<TM;m++)
        #pragma unroll
        for (int n=0;n<TN;n++) acc[m][n]=0.f;

    int arow = tid >> 1, acol = (tid & 1) * 4;
    int brow = tid >> 5, bcol = (tid & 31) * 4;
    const bool aok = (bm + arow) < M;
    const bool bok = (bn + bcol) < N;

    for (int k0 = 0; k0 < K; k0 += BK) {
        float4 av = make_float4(0.f,0.f,0.f,0.f);
        if (aok) av = *(const float4*)(A + (size_t)(bm+arow)*lda + (k0+acol));
        As[acol+0][arow]=av.x; As[acol+1][arow]=av.y;
        As[acol+2][arow]=av.z; As[acol+3][arow]=av.w;
        float4 bv = make_float4(0.f,0.f,0.f,0.f);
        if (bok) bv = *(const float4*)(B + (size_t)(k0+brow)*ldb + (bn+bcol));
        *(float4*)&Bs[brow][bcol] = bv;
        __syncthreads();
        #pragma unroll
        for (int kk=0; kk<BK; kk++) {
            float4 a0 = *(const float4*)&As[kk][ty*TM];
            float4 a1 = *(const float4*)&As[kk][ty*TM+4];
            float4 b0 = *(const float4*)&Bs[kk][tx*TN];
            float4 b1 = *(const float4*)&Bs[kk][tx*TN+4];
            float ar[TM] = {a0.x,a0.y,a0.z,a0.w,a1.x,a1.y,a1.z,a1.w};
            float br[TN] = {b0.x,b0.y,b0.z,b0.w,b1.x,b1.y,b1.z,b1.w};
            #pragma unroll
            for (int m=0;m<TM;m++)
                #pragma unroll
                for (int n=0;n<TN;n++)
                    acc[m][n] += ar[m]*br[n];
        }
        __syncthreads();
    }
    float gt = gate ? *gate : 1.0f;
    #pragma unroll
    for (int m=0;m<TM;m++) {
        int row = bm + ty*TM + m;
        if (row >= M) continue;
        #pragma unroll
        for (int n=0;n<TN;n++) {
            int col = bn + tx*TN + n;
            if (col >= N) continue;
            float v = acc[m][n];
            if (bias) v += bias[col];
            C[(size_t)row*ldc + col] = gt * v;
        }
    }
}

// ---------------- kc/vc = shared_{k,v} + sum_r a[b,v,r] * catB_{k,v}[v,r] ----------------
__global__ void __launch_bounds__(256) kcvc_kernel(const int* __restrict__ catids,
                                                   const float* __restrict__ cat_A)
{
    int blk = blockIdx.x;            // b*320 + v*32 + s
    int b = blk / 320, rem = blk % 320;
    int v = rem >> 5, s = rem & 31;
    int cid = catids[b]; if (cid < 0) cid = 0;
    float a[Rx];
    #pragma unroll
    for (int r=0;r<Rx;r++) a[r] = cat_A[(cid*Sx + v)*Rx + r];
    int c = threadIdx.x * 4;
    size_t base_sc = ((size_t)(v*SLOTSx + s))*Cx + c;
    float4 ka = *(const float4*)(g_sk + base_sc);
    float4 va = *(const float4*)(g_sv + base_sc);
    #pragma unroll
    for (int r=0;r<Rx;r++) {
        size_t idx = ((size_t)((v*Rx + r)*SLOTSx + s))*Cx + c;
        float4 kb = *(const float4*)(g_cbk + idx);
        float4 vb = *(const float4*)(g_cbv + idx);
        ka.x += a[r]*kb.x; ka.y += a[r]*kb.y; ka.z += a[r]*kb.z; ka.w += a[r]*kb.w;
        va.x += a[r]*vb.x; va.y += a[r]*vb.y; va.z += a[r]*vb.z; va.w += a[r]*vb.w;
    }
    size_t o = ((size_t)(b*320 + v*SLOTSx + s))*Cx + c;
    *(float4*)(g_kc + o) = ka;
    *(float4*)(g_vc + o) = va;
}

// ---------------- alpha constant tables ----------------
__global__ void aconst_kernel(const float* __restrict__ cat_emb,
                              const float* __restrict__ scale_emb,
                              const float* __restrict__ aW1,
                              const float* __restrict__ ab1)
{
    int idx = blockIdx.x;
    int h = threadIdx.x;   // 128 threads
    if (idx < NCATx) {
        float acc = 0.f;
        const float* ce = cat_emb + (size_t)idx * Cx;
        for (int c = 0; c < Cx; c++)
            acc += ce[c] * aW1[(size_t)(Cx + c)*AHx + h];
        g_acat[idx*AHx + h] = acc;
    } else {
        int i = idx - NCATx;
        float acc = ab1[h];
        const float* se = scale_emb + (size_t)i * Cx;
        for (int c = 0; c < Cx; c++)
            acc += se[c] * aW1[(size_t)(2*Cx + c)*AHx + h];
        g_ascale[i*AHx + h] = acc;
    }
}

// ---------------- fused attention + alpha blend ----------------
__global__ void __launch_bounds__(256) attn_kernel(const int* __restrict__ catids,
                                                   const float* __restrict__ aW2,
                                                   const float* __restrict__ ab2)
{
    constexpr int ST = NKMAX;   // 320
    extern __shared__ float sm[];
    float* qs  = sm;                  // TQ*1024
    float* os  = qs + TQ*Cx;          // TQ*1024
    float* lg  = os + TQ*Cx;          // TQ*320
    float* alp = lg + TQ*ST;          // TQ

    int tid = threadIdx.x, lane = tid & 31, w = tid >> 5;
    int tile = blockIdx.x, b = blockIdx.y;
    int i = 0;
    #pragma unroll
    for (int u = 1; u < 10; u++) if (tile >= c_cumt[u]) i = u;
    int t = tile - c_cumt[i];
    int q0 = c_begin[i] + t*TQ;
    int rows = c_len[i] - t*TQ; if (rows > TQ) rows = TQ;
    int nk = (i + 1) * SLOTSx;
    float lscale = g_scal[0];

    // load Q tile (zeros for padded rows)
    {
        const float4* qg = (const float4*)(g_query + ((size_t)(b*Lx + q0))*Cx);
        float4* qs4 = (float4*)qs;
        for (int u = tid; u < TQ*256; u += 256) {
            int r = u >> 8;
            float4 v = make_float4(0.f,0.f,0.f,0.f);
            if (r < rows) v = qg[(size_t)r*256 + (u & 255)];
            qs4[u] = v;
        }
    }

    // alpha gate per row
    bool valid = catids[b] >= 0;
    int cid = catids[b]; if (cid < 0) cid = 0;
    for (int r = w; r < TQ; r += 8) {
        float accv = 0.f;
        if (r < rows && valid) {
            const float* qhp = g_qh + ((size_t)(b*Lx + q0 + r))*AHx;
            const float* acp = g_acat + cid*AHx;
            const float* asp = g_ascale + i*AHx;
            #pragma unroll
            for (int hh = lane; hh < AHx; hh += 32) {
                float xv = qhp[hh] + acp[hh] + asp[hh];
                float ge = 0.5f*xv*(1.0f + erff(xv*0.70710678118654752f));
                accv += ge * aW2[hh];
            }
            #pragma unroll
            for (int o = 16; o > 0; o >>= 1) accv += __shfl_xor_sync(0xffffffffu, accv, o);
        }
        if (lane == 0) alp[r] = (r < rows && valid) ? (1.0f/(1.0f + expf(-(accv + ab2[0])))) : 0.0f;
    }
    __syncthreads();

    for (int set = 0; set < 2; set++) {
        const float* Kmat = set ? (g_kc + (size_t)b*NKMAX*Cx) : g_sk;
        const float* Vmat = set ? (g_vc + (size_t)b*NKMAX*Cx) : g_sv;

        // logits: one key per warp, keys in registers
        for (int j = w; j < nk; j += 8) {
            const float4* kr = (const float4*)(Kmat + (size_t)j*Cx);
            float4 kv[8];
            #pragma unroll
            for (int u = 0; u < 8; u++) kv[u] = kr[lane + 32*u];
            for (int r = 0; r < TQ; r++) {
                const float4* q4 = (const float4*)(qs + r*Cx);
                float acc = 0.f;
                #pragma unroll
                for (int u = 0; u < 8; u++) {
                    float4 qv = q4[lane + 32*u];
                    acc += kv[u].x*qv.x + kv[u].y*qv.y + kv[u].z*qv.z + kv[u].w*qv.w;
                }
                #pragma unroll
                for (int o = 16; o > 0; o >>= 1) acc += __shfl_xor_sync(0xffffffffu, acc, o);
                if (lane == 0) lg[r*ST + j] = acc * lscale;
            }
        }
        __syncthreads();

        // softmax rows
        for (int r = w; r < TQ; r += 8) {
            float* row = lg + r*ST;
            float m = -3.4e38f;
            for (int j = lane; j < nk; j += 32) m = fmaxf(m, row[j]);
            #pragma unroll
            for (int o = 16; o > 0; o >>= 1) m = fmaxf(m, __shfl_xor_sync(0xffffffffu, m, o));
            float sacc = 0.f;
            for (int j = lane; j < nk; j += 32) { float e = expf(row[j] - m); row[j] = e; sacc += e; }
            #pragma unroll
            for (int o = 16; o > 0; o >>= 1) sacc += __shfl_xor_sync(0xffffffffu, sacc, o);
            float inv = 1.0f / sacc;
            for (int j = lane; j < nk; j += 32) row[j] *= inv;
        }
        __syncthreads();

        // O = P @ V, 8 rows x float4(col) per thread per pass
        const float4* V4 = (const float4*)Vmat;
        float4* os4 = (float4*)os;
        for (int rh = 0; rh < 2; rh++) {
            float4 acc[8];
            #pragma unroll
            for (int u = 0; u < 8; u++) acc[u] = make_float4(0.f,0.f,0.f,0.f);
            for (int j = 0; j < nk; j++) {
                float4 v = V4[(size_t)j*256 + tid];
                #pragma unroll
                for (int rr = 0; rr < 8; rr++) {
                    float p = lg[(rh*8 + rr)*ST + j];
                    acc[rr].x += p*v.x; acc[rr].y += p*v.y;
                    acc[rr].z += p*v.z; acc[rr].w += p*v.w;
                }
            }
            if (set == 0) {
                #pragma unroll
                for (int rr = 0; rr < 8; rr++) os4[(rh*8 + rr)*256 + tid] = acc[rr];
            } else {
                #pragma unroll
                for (int rr = 0; rr < 8; rr++) {
                    int r = rh*8 + rr;
                    if (r < rows) {
                        float a = alp[r];
                        float4 o0 = os4[r*256 + tid];
                        float4 out;
                        out.x = o0.x + a*(acc[rr].x - o0.x);
                        out.y = o0.y + a*(acc[rr].y - o0.y);
                        out.z = o0.z + a*(acc[rr].z - o0.z);
                        out.w = o0.w + a*(acc[rr].w - o0.w);
                        ((float4*)(g_mem + ((size_t)(b*Lx + q0 + r))*Cx))[tid] = out;
                    }
                }
            }
        }
        __syncthreads();
    }
}

// ---------------- tail: zero scalars / leftover ----------------
__global__ void tail_kernel(float* out, int n2, int total) {
    int idx = n2 + blockIdx.x*blockDim.x + threadIdx.x;
    if (idx < total) out[idx] = 0.f;
}

// ---------------- launch ----------------
extern "C" void kernel_launch(void* const* d_in, const int* in_sizes, int n_in,
                              void* d_out, int out_size) {
    const float* x        = (const float*)d_in[0];
    const int*   catids   = (const int*)  d_in[1];
    const float* shmem    = (const float*)d_in[2];
    const float* cat_A    = (const float*)d_in[3];
    const float* cat_B    = (const float*)d_in[4];
    const float* cat_emb  = (const float*)d_in[5];
    const float* scale_emb= (const float*)d_in[6];
    const float* Wq       = (const float*)d_in[7];
    const float* Wk       = (const float*)d_in[8];
    const float* Wv       = (const float*)d_in[9];
    const float* aW1      = (const float*)d_in[10];
    const float* ab1      = (const float*)d_in[11];
    const float* aW2      = (const float*)d_in[12];
    const float* ab2      = (const float*)d_in[13];
    const float* kW1      = (const float*)d_in[14];
    const float* kb1      = (const float*)d_in[15];
    const float* kW2      = (const float*)d_in[16];
    const float* kb2      = (const float*)d_in[17];
    const float* vW1      = (const float*)d_in[18];
    const float* vb1      = (const float*)d_in[19];
    const float* vW2      = (const float*)d_in[20];
    const float* vb2      = (const float*)d_in[21];
    const float* gk       = (const float*)d_in[22];
    const float* gv       = (const float*)d_in[23];
    const float* lt       = (const float*)d_in[24];

    float *p_query, *p_qh, *p_sk, *p_sv, *p_cbk, *p_cbv, *p_mem, *p_t1k, *p_t1v, *p_scal;
    cudaGetSymbolAddress((void**)&p_query, g_query);
    cudaGetSymbolAddress((void**)&p_qh,    g_qh);
    cudaGetSymbolAddress((void**)&p_sk,    g_sk);
    cudaGetSymbolAddress((void**)&p_sv,    g_sv);
    cudaGetSymbolAddress((void**)&p_cbk,   g_cbk);
    cudaGetSymbolAddress((void**)&p_cbv,   g_cbv);
    cudaGetSymbolAddress((void**)&p_mem,   g_mem);
    cudaGetSymbolAddress((void**)&p_t1k,   g_t1k);
    cudaGetSymbolAddress((void**)&p_t1v,   g_t1v);
    cudaGetSymbolAddress((void**)&p_scal,  g_scal);

    prep_kernel<<<1, 1>>>(gk, gv, lt);

    // query = x @ Wq
    sgemm_kernel<<<dim3(8, 170), 256>>>(NROW, Cx, Cx, x, Cx, Wq, Cx, p_query, Cx, nullptr, nullptr);
    // shared_k / shared_v
    sgemm_kernel<<<dim3(8, 3), 256>>>(Sx*SLOTSx, Cx, Cx, shmem, Cx, Wk, Cx, p_sk, Cx, nullptr, nullptr);
    sgemm_kernel<<<dim3(8, 3), 256>>>(Sx*SLOTSx, Cx, Cx, shmem, Cx, Wv, Cx, p_sv, Cx, nullptr, nullptr);
    // catB_k / catB_v  (cat_B viewed as 2560 x 1024)
    sgemm_kernel<<<dim3(8, 20), 256>>>(Sx*Rx*SLOTSx, Cx, Cx, cat_B, Cx, Wk, Cx, p_cbk, Cx, nullptr, nullptr);
    sgemm_kernel<<<dim3(8, 20), 256>>>(Sx*Rx*SLOTSx, Cx, Cx, cat_B, Cx, Wv, Cx, p_cbv, Cx, nullptr, nullptr);
    // qh = query @ aW1[:1024, :]
    sgemm_kernel<<<dim3(1, 170), 256>>>(NROW, AHx, Cx, p_query, Cx, aW1, AHx, p_qh, AHx, nullptr, nullptr);
    // per-batch kc/vc
    kcvc_kernel<<<Bx*Sx*SLOTSx, 256>>>(catids, cat_A);
    // alpha constants
    aconst_kernel<<<NCATx + Sx, AHx>>>(cat_emb, scale_emb, aW1, ab1);

    // fused attention
    int smem_bytes = (TQ*Cx*2 + TQ*NKMAX + TQ) * (int)sizeof(float);   // ~152 KB
    cudaFuncSetAttribute(attn_kernel, cudaFuncAttributeMaxDynamicSharedMemorySize, smem_bytes);
    attn_kernel<<<dim3(47, Bx), 256, smem_bytes>>>(catids, aW2, ab2);

    // final low-rank projections
    float* outk = (float*)d_out;
    float* outv = (float*)d_out + (size_t)NROW * Cx;
    sgemm_kernel<<<dim3(1, 170), 256>>>(NROW, MRx, Cx, p_mem, Cx, kW1, MRx, p_t1k, MRx, kb1, nullptr);
    sgemm_kernel<<<dim3(1, 170), 256>>>(NROW, MRx, Cx, p_mem, Cx, vW1, MRx, p_t1v, MRx, vb1, nullptr);
    sgemm_kernel<<<dim3(8, 170), 256>>>(NROW, Cx, MRx, p_t1k, MRx, kW2, Cx, outk, Cx, kb2, p_scal + 1);
    sgemm_kernel<<<dim3(8, 170), 256>>>(NROW, Cx, MRx, p_t1v, MRx, vW2, Cx, outv, Cx, vb2, p_scal + 2);

    // zero the two trailing scalar outputs (and anything beyond 2*N*C)
    tail_kernel<<<1, 256>>>((float*)d_out, 2 * NROW * Cx, out_size);
}

// round 2
// speedup vs baseline: 3.1747x; 3.1747x over previous
#include <cuda_runtime.h>
#include <math.h>

// ---------------- problem constants ----------------
static constexpr int Bx = 32, Lx = 680, Cx = 1024;
static constexpr int Sx = 10, SLOTSx = 32, Rx = 8, NCATx = 22;
static constexpr int MRx = 64, AHx = 128;
static constexpr int NROW = Bx * Lx;            // 21760
static constexpr int NKMAX = Sx * SLOTSx;       // 320

__constant__ int c_begin[10] = {0,1,5,14,30,55,91,155,255,424};

// ---------------- device scratch ----------------
__device__ float g_query[NROW * Cx];
__device__ float g_qh[NROW * AHx];
__device__ float g_sk[NKMAX * Cx];
__device__ float g_sv[NKMAX * Cx];
__device__ float g_cbk[Sx * Rx * SLOTSx * Cx];
__device__ float g_cbv[Sx * Rx * SLOTSx * Cx];
__device__ float g_kc[Bx * NKMAX * Cx];
__device__ float g_vc[Bx * NKMAX * Cx];
__device__ float g_lgs[NROW * NKMAX];
__device__ float g_lgc[NROW * NKMAX];
__device__ float g_acat[NCATx * AHx];
__device__ float g_ascale[Sx * AHx];
__device__ float g_alpha[NROW];
__device__ float g_mem[NROW * Cx];
__device__ float g_t1k[NROW * MRx];
__device__ float g_t1v[NROW * MRx];
__device__ float g_scal[4];   // [0]=logit scale, [1]=sig(gk), [2]=sig(gv)

// ---------------- prep ----------------
__global__ void prep_kernel(const float* gk, const float* gv, const float* lt) {
    float temp = expf(lt[0]);
    temp = fminf(fmaxf(temp, 0.05f), 1.0f);
    g_scal[0] = (1.0f / 32.0f) / temp;
    g_scal[1] = 1.0f / (1.0f + expf(-gk[0]));
    g_scal[2] = 1.0f / (1.0f + expf(-gv[0]));
}

// ---------------- tf32 helpers ----------------
__device__ __forceinline__ void split_tf32(float x, unsigned& hi, unsigned& lo) {
    unsigned h; asm("cvt.rna.tf32.f32 %0, %1;" : "=r"(h) : "f"(x));
    float hf = __uint_as_float(h);
    unsigned l; asm("cvt.rna.tf32.f32 %0, %1;" : "=r"(l) : "f"(x - hf));
    hi = h; lo = l;
}

__device__ __forceinline__ void mma8(float* d, const unsigned* a, const unsigned* b) {
    asm volatile(
        "mma.sync.aligned.m16n8k8.row.col.f32.tf32.tf32.f32 "
        "{%0,%1,%2,%3}, {%4,%5,%6,%7}, {%8,%9}, {%0,%1,%2,%3};"
        : "+f"(d[0]), "+f"(d[1]), "+f"(d[2]), "+f"(d[3])
        : "r"(a[0]), "r"(a[1]), "r"(a[2]), "r"(a[3]), "r"(b[0]), "r"(b[1]));
}

// ---------------- 3xTF32 GEMM: C = [accum +] [gate*] (A@B(^T) [+bias]) ----------------
// 128x128x16 tile, 256 threads (8 warps of 64x32), fp32 in/out.
__global__ void __launch_bounds__(256, 2) mma_gemm(
    int M, int N, int K,
    const float* __restrict__ A, int lda, long long sA,
    const float* __restrict__ B, int ldb, long long sB, int transB,
    float* __restrict__ C, int ldc, long long sC,
    const float* __restrict__ bias,
    const float* __restrict__ gate, int accum)
{
    __shared__ unsigned Ah[16][136], Al[16][136], Bh[16][136], Bl[16][136];

    A += (size_t)blockIdx.z * sA;
    B += (size_t)blockIdx.z * sB;
    C += (size_t)blockIdx.z * sC;

    const int tid = threadIdx.x;
    const int bm = blockIdx.y * 128;
    const int bn = blockIdx.x * 128;
    const int lane = tid & 31, wid = tid >> 5;
    const int wm = wid >> 2, wn = wid & 3;         // 2 x 4 warp grid
    const int tg = lane & 3, gid = lane >> 2;

    float acc[4][4][4];
    #pragma unroll
    for (int mt = 0; mt < 4; mt++)
        #pragma unroll
        for (int nt = 0; nt < 4; nt++)
            #pragma unroll
            for (int u = 0; u < 4; u++) acc[mt][nt][u] = 0.f;

    for (int k0 = 0; k0 < K; k0 += 16) {
        __syncthreads();
        // --- A tile 128x16 -> Ah/Al[k][m] (transposed) ---
        #pragma unroll
        for (int u0 = 0; u0 < 2; u0++) {
            int u = tid + u0 * 256;
            int row = u >> 2, c4 = (u & 3) * 4;
            float4 v = make_float4(0.f,0.f,0.f,0.f);
            if (bm + row < M) v = *(const float4*)(A + (size_t)(bm+row)*lda + k0 + c4);
            unsigned h, l;
            split_tf32(v.x, h, l); Ah[c4+0][row] = h; Al[c4+0][row] = l;
            split_tf32(v.y, h, l); Ah[c4+1][row] = h; Al[c4+1][row] = l;
            split_tf32(v.z, h, l); Ah[c4+2][row] = h; Al[c4+2][row] = l;
            split_tf32(v.w, h, l); Ah[c4+3][row] = h; Al[c4+3][row] = l;
        }
        // --- B tile 16x128 -> Bh/Bl[k][n] ---
        if (!transB) {
            #pragma unroll
            for (int u0 = 0; u0 < 2; u0++) {
                int u = tid + u0 * 256;
                int kr = u >> 5, c4 = (u & 31) * 4;
                float4 v = make_float4(0.f,0.f,0.f,0.f);
                if (bn + c4 < N) v = *(const float4*)(B + (size_t)(k0+kr)*ldb + bn + c4);
                unsigned h0,l0,h1,l1,h2,l2,h3,l3;
                split_tf32(v.x,h0,l0); split_tf32(v.y,h1,l1);
                split_tf32(v.z,h2,l2); split_tf32(v.w,h3,l3);
                *(uint4*)&Bh[kr][c4] = make_uint4(h0,h1,h2,h3);
                *(uint4*)&Bl[kr][c4] = make_uint4(l0,l1,l2,l3);
            }
        } else {   // B is [N,K] row-major
            #pragma unroll
            for (int u0 = 0; u0 < 2; u0++) {
                int u = tid + u0 * 256;
                int n = u >> 2, c4 = (u & 3) * 4;
                float4 v = make_float4(0.f,0.f,0.f,0.f);
                if (bn + n < N) v = *(const float4*)(B + (size_t)(bn+n)*ldb + k0 + c4);
                unsigned h, l;
                split_tf32(v.x,h,l); Bh[c4+0][n]=h; Bl[c4+0][n]=l;
                split_tf32(v.y,h,l); Bh[c4+1][n]=h; Bl[c4+1][n]=l;
                split_tf32(v.z,h,l); Bh[c4+2][n]=h; Bl[c4+2][n]=l;
                split_tf32(v.w,h,l); Bh[c4+3][n]=h; Bl[c4+3][n]=l;
            }
        }
        __syncthreads();

        #pragma unroll
        for (int kk = 0; kk < 16; kk += 8) {
            unsigned bh[4][2], bl[4][2];
            #pragma unroll
            for (int nt = 0; nt < 4; nt++) {
                int cb = wn*32 + nt*8 + gid;
                bh[nt][0] = Bh[kk+tg][cb];   bh[nt][1] = Bh[kk+tg+4][cb];
                bl[nt][0] = Bl[kk+tg][cb];   bl[nt][1] = Bl[kk+tg+4][cb];
            }
            #pragma unroll
            for (int mt = 0; mt < 4; mt++) {
                int rb = wm*64 + mt*16 + gid;
                unsigned ah[4] = {Ah[kk+tg][rb], Ah[kk+tg][rb+8],
                                  Ah[kk+tg+4][rb], Ah[kk+tg+4][rb+8]};
                unsigned al[4] = {Al[kk+tg][rb], Al[kk+tg][rb+8],
                                  Al[kk+tg+4][rb], Al[kk+tg+4][rb+8]};
                #pragma unroll
                for (int nt = 0; nt < 4; nt++) {
                    mma8(acc[mt][nt], ah, bh[nt]);
                    mma8(acc[mt][nt], ah, bl[nt]);
                    mma8(acc[mt][nt], al, bh[nt]);
                }
            }
        }
    }

    const float gt = gate ? *gate : 1.0f;
    #pragma unroll
    for (int mt = 0; mt < 4; mt++) {
        int r0 = bm + wm*64 + mt*16 + gid;
        int r1 = r0 + 8;
        #pragma unroll
        for (int nt = 0; nt < 4; nt++) {
            int col = bn + wn*32 + nt*8 + 2*tg;
            if (col >= N) continue;
            float b0 = bias ? bias[col] : 0.f;
            float b1 = bias ? bias[col+1] : 0.f;
            if (r0 < M) {
                float v0 = gt * (acc[mt][nt][0] + b0);
                float v1 = gt * (acc[mt][nt][1] + b1);
                float* p = C + (size_t)r0*ldc + col;
                if (accum) { v0 += p[0]; v1 += p[1]; }
                *(float2*)p = make_float2(v0, v1);
            }
            if (r1 < M) {
                float v0 = gt * (acc[mt][nt][2] + b0);
                float v1 = gt * (acc[mt][nt][3] + b1);
                float* p = C + (size_t)r1*ldc + col;
                if (accum) { v0 += p[0]; v1 += p[1]; }
                *(float2*)p = make_float2(v0, v1);
            }
        }
    }
}

// ---------------- kc/vc broadcast ----------------
__global__ void __launch_bounds__(256) kcvc_kernel(const int* __restrict__ catids,
                                                   const float* __restrict__ cat_A)
{
    int blk = blockIdx.x;
    int b = blk / 320, rem = blk % 320;
    int v = rem >> 5, s = rem & 31;
    int cid = catids[b]; if (cid < 0) cid = 0;
    float a[Rx];
    #pragma unroll
    for (int r=0;r<Rx;r++) a[r] = cat_A[(cid*Sx + v)*Rx + r];
    int c = threadIdx.x * 4;
    size_t base_sc = ((size_t)(v*SLOTSx + s))*Cx + c;
    float4 ka = *(const float4*)(g_sk + base_sc);
    float4 va = *(const float4*)(g_sv + base_sc);
    #pragma unroll
    for (int r=0;r<Rx;r++) {
        size_t idx = ((size_t)((v*Rx + r)*SLOTSx + s))*Cx + c;
        float4 kb = *(const float4*)(g_cbk + idx);
        float4 vb = *(const float4*)(g_cbv + idx);
        ka.x += a[r]*kb.x; ka.y += a[r]*kb.y; ka.z += a[r]*kb.z; ka.w += a[r]*kb.w;
        va.x += a[r]*vb.x; va.y += a[r]*vb.y; va.z += a[r]*vb.z; va.w += a[r]*vb.w;
    }
    size_t o = ((size_t)(b*320 + v*SLOTSx + s))*Cx + c;
    *(float4*)(g_kc + o) = ka;
    *(float4*)(g_vc + o) = va;
}

// ---------------- alpha constant tables ----------------
__global__ void aconst_kernel(const float* __restrict__ cat_emb,
                              const float* __restrict__ scale_emb,
                              const float* __restrict__ aW1,
                              const float* __restrict__ ab1)
{
    int idx = blockIdx.x;
    int h = threadIdx.x;   // 128 threads
    if (idx < NCATx) {
        float acc = 0.f;
        const float* ce = cat_emb + (size_t)idx * Cx;
        for (int c = 0; c < Cx; c++)
            acc += ce[c] * aW1[(size_t)(Cx + c)*AHx + h];
        g_acat[idx*AHx + h] = acc;
    } else {
        int i = idx - NCATx;
        float acc = ab1[h];
        const float* se = scale_emb + (size_t)i * Cx;
        for (int c = 0; c < Cx; c++)
            acc += se[c] * aW1[(size_t)(2*Cx + c)*AHx + h];
        g_ascale[i*AHx + h] = acc;
    }
}

// ---------------- alpha gate per row ----------------
__global__ void __launch_bounds__(256) alpha_kernel(const int* __restrict__ catids,
                                                    const float* __restrict__ aW2,
                                                    const float* __restrict__ ab2)
{
    int w = threadIdx.x >> 5, lane = threadIdx.x & 31;
    int row = blockIdx.x * 8 + w;
    if (row >= NROW) return;
    int b = row / Lx, l = row % Lx;
    int cid = catids[b];
    if (cid < 0) { if (lane == 0) g_alpha[row] = 0.f; return; }
    int i = 0;
    #pragma unroll
    for (int u = 1; u < 10; u++) if (l >= c_begin[u]) i = u;
    const float* qhp = g_qh + (size_t)row*AHx;
    const float* ac  = g_acat + cid*AHx;
    const float* as  = g_ascale + i*AHx;
    float acc = 0.f;
    #pragma unroll
    for (int h = lane; h < AHx; h += 32) {
        float xv = qhp[h] + ac[h] + as[h];
        float ge = 0.5f*xv*(1.0f + erff(xv*0.70710678118654752f));
        acc += ge * aW2[h];
    }
    #pragma unroll
    for (int o = 16; o > 0; o >>= 1) acc += __shfl_xor_sync(0xffffffffu, acc, o);
    if (lane == 0) g_alpha[row] = 1.0f/(1.0f + expf(-(acc + ab2[0])));
}

// ---------------- masked softmax + alpha prescale (in place) ----------------
__global__ void __launch_bounds__(256) softmax_kernel()
{
    int w = threadIdx.x >> 5, lane = threadIdx.x & 31;
    int row = blockIdx.x * 8 + w;
    if (row >= NROW) return;
    int l = row % Lx;
    int i = 0;
    #pragma unroll
    for (int u = 1; u < 10; u++) if (l >= c_begin[u]) i = u;
    int nk = (i + 1) * SLOTSx;
    float ls = g_scal[0];
    float a = g_alpha[row];
    #pragma unroll
    for (int s = 0; s < 2; s++) {
        float* p = (s ? g_lgc : g_lgs) + (size_t)row * NKMAX;
        float wgt = s ? a : (1.0f - a);
        float v[10];
        int cnt = 0;
        float mx = -3.4e38f;
        for (int j = lane; j < nk; j += 32) { float t = p[j]*ls; v[cnt++] = t; mx = fmaxf(mx, t); }
        #pragma unroll
        for (int o = 16; o > 0; o >>= 1) mx = fmaxf(mx, __shfl_xor_sync(0xffffffffu, mx, o));
        float sum = 0.f;
        for (int c2 = 0; c2 < cnt; c2++) { v[c2] = expf(v[c2] - mx); sum += v[c2]; }
        #pragma unroll
        for (int o = 16; o > 0; o >>= 1) sum += __shfl_xor_sync(0xffffffffu, sum, o);
        float inv = wgt / sum;
        cnt = 0;
        for (int j = lane; j < NKMAX; j += 32)
            p[j] = (j < nk) ? v[cnt++] * inv : 0.f;
    }
}

// ---------------- tail ----------------
__global__ void tail_kernel(float* out, int n2, int total) {
    int idx = n2 + blockIdx.x*blockDim.x + threadIdx.x;
    if (idx < total) out[idx] = 0.f;
}

// ---------------- launch ----------------
extern "C" void kernel_launch(void* const* d_in, const int* in_sizes, int n_in,
                              void* d_out, int out_size) {
    const float* x        = (const float*)d_in[0];
    const int*   catids   = (const int*)  d_in[1];
    const float* shmem    = (const float*)d_in[2];
    const float* cat_A    = (const float*)d_in[3];
    const float* cat_B    = (const float*)d_in[4];
    const float* cat_emb  = (const float*)d_in[5];
    const float* scale_emb= (const float*)d_in[6];
    const float* Wq       = (const float*)d_in[7];
    const float* Wk       = (const float*)d_in[8];
    const float* Wv       = (const float*)d_in[9];
    const float* aW1      = (const float*)d_in[10];
    const float* ab1      = (const float*)d_in[11];
    const float* aW2      = (const float*)d_in[12];
    const float* ab2      = (const float*)d_in[13];
    const float* kW1      = (const float*)d_in[14];
    const float* kb1      = (const float*)d_in[15];
    const float* kW2      = (const float*)d_in[16];
    const float* kb2      = (const float*)d_in[17];
    const float* vW1      = (const float*)d_in[18];
    const float* vb1      = (const float*)d_in[19];
    const float* vW2      = (const float*)d_in[20];
    const float* vb2      = (const float*)d_in[21];
    const float* gk       = (const float*)d_in[22];
    const float* gv       = (const float*)d_in[23];
    const float* lt       = (const float*)d_in[24];

    float *p_query,*p_qh,*p_sk,*p_sv,*p_cbk,*p_cbv,*p_kc,*p_vc,*p_lgs,*p_lgc,*p_mem,*p_t1k,*p_t1v,*p_scal;
    cudaGetSymbolAddress((void**)&p_query, g_query);
    cudaGetSymbolAddress((void**)&p_qh,    g_qh);
    cudaGetSymbolAddress((void**)&p_sk,    g_sk);
    cudaGetSymbolAddress((void**)&p_sv,    g_sv);
    cudaGetSymbolAddress((void**)&p_cbk,   g_cbk);
    cudaGetSymbolAddress((void**)&p_cbv,   g_cbv);
    cudaGetSymbolAddress((void**)&p_kc,    g_kc);
    cudaGetSymbolAddress((void**)&p_vc,    g_vc);
    cudaGetSymbolAddress((void**)&p_lgs,   g_lgs);
    cudaGetSymbolAddress((void**)&p_lgc,   g_lgc);
    cudaGetSymbolAddress((void**)&p_mem,   g_mem);
    cudaGetSymbolAddress((void**)&p_t1k,   g_t1k);
    cudaGetSymbolAddress((void**)&p_t1v,   g_t1v);
    cudaGetSymbolAddress((void**)&p_scal,  g_scal);

    prep_kernel<<<1, 1>>>(gk, gv, lt);

    // query = x @ Wq                         [21760 x 1024 x 1024]
    mma_gemm<<<dim3(8,170,1),256>>>(NROW, Cx, Cx, x, Cx, 0, Wq, Cx, 0, 0, p_query, Cx, 0, nullptr, nullptr, 0);
    // shared_k / shared_v                    [320 x 1024 x 1024]
    mma_gemm<<<dim3(8,3,1),256>>>(NKMAX, Cx, Cx, shmem, Cx, 0, Wk, Cx, 0, 0, p_sk, Cx, 0, nullptr, nullptr, 0);
    mma_gemm<<<dim3(8,3,1),256>>>(NKMAX, Cx, Cx, shmem, Cx, 0, Wv, Cx, 0, 0, p_sv, Cx, 0, nullptr, nullptr, 0);
    // cat_B @ Wk / Wv                        [2560 x 1024 x 1024]
    mma_gemm<<<dim3(8,20,1),256>>>(2560, Cx, Cx, cat_B, Cx, 0, Wk, Cx, 0, 0, p_cbk, Cx, 0, nullptr, nullptr, 0);
    mma_gemm<<<dim3(8,20,1),256>>>(2560, Cx, Cx, cat_B, Cx, 0, Wv, Cx, 0, 0, p_cbv, Cx, 0, nullptr, nullptr, 0);
    // qh = query @ aW1[:1024]                [21760 x 128 x 1024]
    mma_gemm<<<dim3(1,170,1),256>>>(NROW, AHx, Cx, p_query, Cx, 0, aW1, AHx, 0, 0, p_qh, AHx, 0, nullptr, nullptr, 0);
    // per-batch kc/vc
    kcvc_kernel<<<Bx*NKMAX, 256>>>(catids, cat_A);
    // alpha constants + per-row alpha
    aconst_kernel<<<NCATx + Sx, AHx>>>(cat_emb, scale_emb, aW1, ab1);
    alpha_kernel<<<(NROW + 7)/8, 256>>>(catids, aW2, ab2);

    // logits (NT GEMMs)
    mma_gemm<<<dim3(3,170,1),256>>>(NROW, NKMAX, Cx, p_query, Cx, 0, p_sk, Cx, 0, 1, p_lgs, NKMAX, 0, nullptr, nullptr, 0);
    mma_gemm<<<dim3(3,6,32),256>>>(Lx, NKMAX, Cx, p_query, Cx, (long long)Lx*Cx,
                                   p_kc, Cx, (long long)NKMAX*Cx, 1,
                                   p_lgc, NKMAX, (long long)Lx*NKMAX, nullptr, nullptr, 0);
    // masked softmax with (1-alpha)/alpha prescale
    softmax_kernel<<<(NROW + 7)/8, 256>>>();

    // mem = P_s @ sv + P_c @ vc
    mma_gemm<<<dim3(8,170,1),256>>>(NROW, Cx, NKMAX, p_lgs, NKMAX, 0, p_sv, Cx, 0, 0, p_mem, Cx, 0, nullptr, nullptr, 0);
    mma_gemm<<<dim3(8,6,32),256>>>(Lx, Cx, NKMAX, p_lgc, NKMAX, (long long)Lx*NKMAX,
                                   p_vc, Cx, (long long)NKMAX*Cx, 0,
                                   p_mem, Cx, (long long)Lx*Cx, nullptr, nullptr, 1);

    // low-rank heads
    float* outk = (float*)d_out;
    float* outv = (float*)d_out + (size_t)NROW * Cx;
    mma_gemm<<<dim3(1,170,1),256>>>(NROW, MRx, Cx, p_mem, Cx, 0, kW1, MRx, 0, 0, p_t1k, MRx, 0, kb1, nullptr, 0);
    mma_gemm<<<dim3(1,170,1),256>>>(NROW, MRx, Cx, p_mem, Cx, 0, vW1, MRx, 0, 0, p_t1v, MRx, 0, vb1, nullptr, 0);
    mma_gemm<<<dim3(8,170,1),256>>>(NROW, Cx, MRx, p_t1k, MRx, 0, kW2, Cx, 0, 0, outk, Cx, 0, kb2, p_scal+1, 0);
    mma_gemm<<<dim3(8,170,1),256>>>(NROW, Cx, MRx, p_t1v, MRx, 0, vW2, Cx, 0, 0, outv, Cx, 0, vb2, p_scal+2, 0);

    tail_kernel<<<1, 256>>>((float*)d_out, 2 * NROW * Cx, out_size);
}

// round 3
// speedup vs baseline: 4.2353x; 1.3341x over previous
#include <cuda_runtime.h>
#include <math.h>

// ---------------- problem constants ----------------
static constexpr int Bx = 32, Lx = 680, Cx = 1024;
static constexpr int Sx = 10, SLOTSx = 32, Rx = 8, NCATx = 22;
static constexpr int MRx = 64, AHx = 128;
static constexpr int NROW = Bx * Lx;            // 21760
static constexpr int NKMAX = Sx * SLOTSx;       // 320
static constexpr int NQ = NROW * Cx;            // 22282240

__constant__ int c_begin[10] = {0,1,5,14,30,55,91,155,255,424};

// ---------------- device scratch (split planes are u32 tf32 bit patterns) ----------------
__device__ unsigned g_xs_h[NQ], g_xs_l[NQ];
__device__ unsigned g_qs_h[NQ], g_qs_l[NQ];
__device__ unsigned g_Wq_h[Cx*Cx], g_Wq_l[Cx*Cx];
__device__ unsigned g_Wk_h[Cx*Cx], g_Wk_l[Cx*Cx];
__device__ unsigned g_Wv_h[Cx*Cx], g_Wv_l[Cx*Cx];
__device__ unsigned g_aW1_h[Cx*AHx], g_aW1_l[Cx*AHx];
__device__ unsigned g_shm_h[NKMAX*Cx], g_shm_l[NKMAX*Cx];
__device__ unsigned g_cB_h[2560*Cx], g_cB_l[2560*Cx];
__device__ unsigned g_kW1_h[Cx*MRx], g_kW1_l[Cx*MRx];
__device__ unsigned g_kW2_h[MRx*Cx], g_kW2_l[MRx*Cx];
__device__ unsigned g_vW1_h[Cx*MRx], g_vW1_l[Cx*MRx];
__device__ unsigned g_vW2_h[MRx*Cx], g_vW2_l[MRx*Cx];

__device__ float    g_skf[NKMAX*Cx], g_svf[NKMAX*Cx];
__device__ unsigned g_sk_h[NKMAX*Cx], g_sk_l[NKMAX*Cx];
__device__ unsigned g_sv_h[NKMAX*Cx], g_sv_l[NKMAX*Cx];
__device__ float    g_cbkf[2560*Cx], g_cbvf[2560*Cx];
__device__ unsigned g_kc_h[Bx*NKMAX*Cx], g_kc_l[Bx*NKMAX*Cx];
__device__ unsigned g_vc_h[Bx*NKMAX*Cx], g_vc_l[Bx*NKMAX*Cx];
__device__ float    g_lgsf[NROW*NKMAX], g_lgcf[NROW*NKMAX];
__device__ unsigned g_lgs_h[NROW*NKMAX], g_lgc_h[NROW*NKMAX];
__device__ float    g_qhf[NROW*AHx];
__device__ float    g_memf[NQ];
__device__ unsigned g_mem_h[NQ], g_mem_l[NQ];
__device__ unsigned g_t1k_h[NROW*MRx], g_t1k_l[NROW*MRx];
__device__ unsigned g_t1v_h[NROW*MRx], g_t1v_l[NROW*MRx];
__device__ float    g_acat[NCATx*AHx];
__device__ float    g_ascale[Sx*AHx];
__device__ float    g_alpha[NROW];
__device__ float    g_scal[4];

// ---------------- helpers ----------------
__device__ __forceinline__ void split_tf32(float x, unsigned& hi, unsigned& lo) {
    unsigned h; asm("cvt.rna.tf32.f32 %0, %1;" : "=r"(h) : "f"(x));
    float hf = __uint_as_float(h);
    unsigned l; asm("cvt.rna.tf32.f32 %0, %1;" : "=r"(l) : "f"(x - hf));
    hi = h; lo = l;
}
__device__ __forceinline__ unsigned to_tf32(float x) {
    unsigned h; asm("cvt.rna.tf32.f32 %0, %1;" : "=r"(h) : "f"(x)); return h;
}
__device__ __forceinline__ void mma8(float* d, const unsigned* a, const unsigned* b) {
    asm volatile(
        "mma.sync.aligned.m16n8k8.row.col.f32.tf32.tf32.f32 "
        "{%0,%1,%2,%3}, {%4,%5,%6,%7}, {%8,%9}, {%0,%1,%2,%3};"
        : "+f"(d[0]), "+f"(d[1]), "+f"(d[2]), "+f"(d[3])
        : "r"(a[0]), "r"(a[1]), "r"(a[2]), "r"(a[3]), "r"(b[0]), "r"(b[1]));
}
__device__ __forceinline__ unsigned smaddr(const void* p) {
    unsigned a;
    asm("{.reg .u64 u; cvta.to.shared.u64 u, %1; cvt.u32.u64 %0, u;}" : "=r"(a) : "l"(p));
    return a;
}
__device__ __forceinline__ void cp16(unsigned dst, const void* src, bool ok) {
    int sz = ok ? 16 : 0;
    asm volatile("cp.async.cg.shared.global [%0], [%1], 16, %2;\n" :: "r"(dst), "l"(src), "r"(sz));
}
__device__ __forceinline__ void cp_commit() { asm volatile("cp.async.commit_group;"); }
template<int N> __device__ __forceinline__ void cp_wait() {
    asm volatile("cp.async.wait_group %0;" :: "n"(N));
}

// ---------------- prep ----------------
__global__ void prep_kernel(const float* gk, const float* gv, const float* lt) {
    float temp = expf(lt[0]);
    temp = fminf(fmaxf(temp, 0.05f), 1.0f);
    g_scal[0] = (1.0f / 32.0f) / temp;
    g_scal[1] = 1.0f / (1.0f + expf(-gk[0]));
    g_scal[2] = 1.0f / (1.0f + expf(-gv[0]));
}

// ---------------- split input fp32 -> hi/lo planes ----------------
__global__ void split_kernel(const float* __restrict__ in, unsigned* __restrict__ hi,
                             unsigned* __restrict__ lo, int n4) {
    int i = blockIdx.x * 256 + threadIdx.x;
    if (i >= n4) return;
    float4 v = ((const float4*)in)[i];
    uint4 h, l;
    split_tf32(v.x, h.x, l.x); split_tf32(v.y, h.y, l.y);
    split_tf32(v.z, h.z, l.z); split_tf32(v.w, h.w, l.w);
    ((uint4*)hi)[i] = h; ((uint4*)lo)[i] = l;
}

// ---------------- GEMM args ----------------
struct GemmArgs {
    int M, N, K;
    const unsigned *Ah, *Al; int lda; long long sA;
    const unsigned *Bh, *Bl; int ldb; long long sB;
    float* Cf;                 // fp32 C plane (read for accum / written if wr_f32)
    unsigned *Chi, *Clo;       // split C planes
    int ldc; long long sC;
    const float* bias;
    const float* gate;
    int accum, wr_f32, wr_split;
};

// ---------------- pipelined 3x/1x TF32 GEMM ----------------
template<int TRANSB, int NPASS>
__global__ void __launch_bounds__(256, 2) gemm_tmpl(GemmArgs g)
{
    constexpr int AW  = 20;                       // A smem row stride (words), conflict-free
    constexpr int BW  = TRANSB ? 20 : 136;
    constexpr int ASZ = 128 * AW;                 // 2560 words / plane
    constexpr int BSZ = TRANSB ? 128 * BW : 16 * BW;
    constexpr int NPL = (NPASS == 3) ? 2 : 1;
    constexpr int STG = NPL * (ASZ + BSZ);        // words per stage
    extern __shared__ unsigned sm[];

    const int tid = threadIdx.x, lane = tid & 31, wid = tid >> 5;
    const int wm = wid >> 2, wn = wid & 3, tg = lane & 3, gid = lane >> 2;
    const int bm = blockIdx.y * 128, bn = blockIdx.x * 128;
    const long long z = blockIdx.z;

    const unsigned* Ap[2];
    Ap[0] = g.Ah + z * g.sA;
    Ap[1] = (NPASS == 3) ? g.Al + z * g.sA : Ap[0];
    const unsigned* Bp[2];
    Bp[0] = g.Bh + z * g.sB;
    Bp[1] = (NPASS == 3) ? g.Bl + z * g.sB : Bp[0];

    const unsigned smbase = smaddr(sm);

    float acc[4][4][4];
    #pragma unroll
    for (int mt = 0; mt < 4; mt++)
        #pragma unroll
        for (int nt = 0; nt < 4; nt++)
            #pragma unroll
            for (int u = 0; u < 4; u++) acc[mt][nt][u] = 0.f;

    auto load_stage = [&](int s, int k0) {
        unsigned ab = smbase + s * STG * 4;
        #pragma unroll
        for (int i = 0; i < 2 * NPL; i++) {
            int c = tid + i * 256;
            int p = c >> 9, rem = c & 511;
            int row = rem >> 2, kc = (rem & 3) * 4;
            bool ok = (bm + row) < g.M;
            const unsigned* src = ok ? Ap[p] + (size_t)(bm + row) * g.lda + k0 + kc : Ap[p];
            cp16(ab + (unsigned)(p * ASZ + row * AW + kc) * 4u, src, ok);
        }
        unsigned bb = smbase + (s * STG + NPL * ASZ) * 4;
        #pragma unroll
        for (int i = 0; i < 2 * NPL; i++) {
            int c = tid + i * 256;
            int p = c >> 9, rem = c & 511;
            if (!TRANSB) {
                int kr = rem >> 5, nc = (rem & 31) * 4;
                bool ok = (bn + nc) < g.N;
                const unsigned* src = ok ? Bp[p] + (size_t)(k0 + kr) * g.ldb + bn + nc : Bp[p];
                cp16(bb + (unsigned)(p * BSZ + kr * BW + nc) * 4u, src, ok);
            } else {
                int n = rem >> 2, kc = (rem & 3) * 4;
                bool ok = (bn + n) < g.N;
                const unsigned* src = ok ? Bp[p] + (size_t)(bn + n) * g.ldb + k0 + kc : Bp[p];
                cp16(bb + (unsigned)(p * BSZ + n * BW + kc) * 4u, src, ok);
            }
        }
    };

    auto compute = [&](int s) {
        const unsigned* As0 = sm + s * STG;
        const unsigned* As1 = As0 + ASZ;
        const unsigned* Bs0 = As0 + NPL * ASZ;
        const unsigned* Bs1 = Bs0 + BSZ;
        #pragma unroll
        for (int kk = 0; kk < 16; kk += 8) {
            unsigned bh[4][2], bl[4][2];
            #pragma unroll
            for (int nt = 0; nt < 4; nt++) {
                int cb = wn * 32 + nt * 8 + gid;
                if (!TRANSB) {
                    bh[nt][0] = Bs0[(kk + tg) * BW + cb];
                    bh[nt][1] = Bs0[(kk + tg + 4) * BW + cb];
                    if (NPASS == 3) {
                        bl[nt][0] = Bs1[(kk + tg) * BW + cb];
                        bl[nt][1] = Bs1[(kk + tg + 4) * BW + cb];
                    }
                } else {
                    bh[nt][0] = Bs0[cb * BW + kk + tg];
                    bh[nt][1] = Bs0[cb * BW + kk + tg + 4];
                    if (NPASS == 3) {
                        bl[nt][0] = Bs1[cb * BW + kk + tg];
                        bl[nt][1] = Bs1[cb * BW + kk + tg + 4];
                    }
                }
            }
            #pragma unroll
            for (int mt = 0; mt < 4; mt++) {
                int rb = wm * 64 + mt * 16 + gid;
                unsigned ah[4] = { As0[rb*AW + kk+tg], As0[(rb+8)*AW + kk+tg],
                                   As0[rb*AW + kk+tg+4], As0[(rb+8)*AW + kk+tg+4] };
                unsigned al[4];
                if (NPASS == 3) {
                    al[0] = As1[rb*AW + kk+tg];   al[1] = As1[(rb+8)*AW + kk+tg];
                    al[2] = As1[rb*AW + kk+tg+4]; al[3] = As1[(rb+8)*AW + kk+tg+4];
                }
                #pragma unroll
                for (int nt = 0; nt < 4; nt++) {
                    mma8(acc[mt][nt], ah, bh[nt]);
                    if (NPASS == 3) {
                        mma8(acc[mt][nt], ah, bl[nt]);
                        mma8(acc[mt][nt], al, bh[nt]);
                    }
                }
            }
        }
    };

    const int nK = g.K >> 4;
    load_stage(0, 0);
    cp_commit();
    for (int kt = 0; kt < nK; kt++) {
        if (kt + 1 < nK) {
            load_stage((kt + 1) & 1, (kt + 1) << 4);
            cp_commit();
            cp_wait<1>();
        } else {
            cp_wait<0>();
        }
        __syncthreads();
        compute(kt & 1);
        __syncthreads();
    }

    // ---------------- epilogue ----------------
    const float gt = g.gate ? *g.gate : 1.0f;
    float* Cf = g.Cf + z * g.sC;
    unsigned* Chi = g.Chi + z * g.sC;
    unsigned* Clo = g.Clo + z * g.sC;
    #pragma unroll
    for (int mt = 0; mt < 4; mt++) {
        int r0 = bm + wm * 64 + mt * 16 + gid;
        int r1 = r0 + 8;
        #pragma unroll
        for (int nt = 0; nt < 4; nt++) {
            int col = bn + wn * 32 + nt * 8 + 2 * tg;
            if (col >= g.N) continue;
            float b0 = g.bias ? g.bias[col]     : 0.f;
            float b1 = g.bias ? g.bias[col + 1] : 0.f;
            #pragma unroll
            for (int half = 0; half < 2; half++) {
                int r = half ? r1 : r0;
                if (r >= g.M) continue;
                size_t o = (size_t)r * g.ldc + col;
                float v0 = gt * (acc[mt][nt][half*2+0] + b0);
                float v1 = gt * (acc[mt][nt][half*2+1] + b1);
                if (g.accum) { v0 += Cf[o]; v1 += Cf[o+1]; }
                if (g.wr_f32) *(float2*)(Cf + o) = make_float2(v0, v1);
                if (g.wr_split) {
                    unsigned h0,l0,h1,l1;
                    split_tf32(v0, h0, l0); split_tf32(v1, h1, l1);
                    Chi[o] = h0; Chi[o+1] = h1;
                    Clo[o] = l0; Clo[o+1] = l1;
                }
            }
        }
    }
}

// ---------------- kc/vc = shared + sum_r a_r * catB_r, write split ----------------
__global__ void __launch_bounds__(256) kcvc_kernel(const int* __restrict__ catids,
                                                   const float* __restrict__ cat_A)
{
    int blk = blockIdx.x;
    int b = blk / 320, rem = blk % 320;
    int v = rem >> 5, s = rem & 31;
    int cid = catids[b]; if (cid < 0) cid = 0;
    float a[Rx];
    #pragma unroll
    for (int r = 0; r < Rx; r++) a[r] = cat_A[(cid*Sx + v)*Rx + r];
    int c = threadIdx.x * 4;
    size_t base_sc = ((size_t)(v*SLOTSx + s))*Cx + c;
    float4 ka = *(const float4*)(g_skf + base_sc);
    float4 va = *(const float4*)(g_svf + base_sc);
    #pragma unroll
    for (int r = 0; r < Rx; r++) {
        size_t idx = ((size_t)((v*Rx + r)*SLOTSx + s))*Cx + c;
        float4 kb = *(const float4*)(g_cbkf + idx);
        float4 vb = *(const float4*)(g_cbvf + idx);
        ka.x += a[r]*kb.x; ka.y += a[r]*kb.y; ka.z += a[r]*kb.z; ka.w += a[r]*kb.w;
        va.x += a[r]*vb.x; va.y += a[r]*vb.y; va.z += a[r]*vb.z; va.w += a[r]*vb.w;
    }
    size_t o = ((size_t)(b*320 + v*SLOTSx + s))*Cx + c;
    uint4 h, l;
    split_tf32(ka.x,h.x,l.x); split_tf32(ka.y,h.y,l.y); split_tf32(ka.z,h.z,l.z); split_tf32(ka.w,h.w,l.w);
    *(uint4*)(g_kc_h + o) = h; *(uint4*)(g_kc_l + o) = l;
    split_tf32(va.x,h.x,l.x); split_tf32(va.y,h.y,l.y); split_tf32(va.z,h.z,l.z); split_tf32(va.w,h.w,l.w);
    *(uint4*)(g_vc_h + o) = h; *(uint4*)(g_vc_l + o) = l;
}

// ---------------- alpha constant tables ----------------
__global__ void aconst_kernel(const float* __restrict__ cat_emb,
                              const float* __restrict__ scale_emb,
                              const float* __restrict__ aW1,
                              const float* __restrict__ ab1)
{
    int idx = blockIdx.x;
    int h = threadIdx.x;
    if (idx < NCATx) {
        float acc = 0.f;
        const float* ce = cat_emb + (size_t)idx * Cx;
        for (int c = 0; c < Cx; c++)
            acc += ce[c] * aW1[(size_t)(Cx + c)*AHx + h];
        g_acat[idx*AHx + h] = acc;
    } else {
        int i = idx - NCATx;
        float acc = ab1[h];
        const float* se = scale_emb + (size_t)i * Cx;
        for (int c = 0; c < Cx; c++)
            acc += se[c] * aW1[(size_t)(2*Cx + c)*AHx + h];
        g_ascale[i*AHx + h] = acc;
    }
}

// ---------------- alpha gate per row ----------------
__global__ void __launch_bounds__(256) alpha_kernel(const int* __restrict__ catids,
                                                    const float* __restrict__ aW2,
                                                    const float* __restrict__ ab2)
{
    int w = threadIdx.x >> 5, lane = threadIdx.x & 31;
    int row = blockIdx.x * 8 + w;
    if (row >= NROW) return;
    int b = row / Lx, l = row % Lx;
    int cid = catids[b];
    if (cid < 0) { if (lane == 0) g_alpha[row] = 0.f; return; }
    int i = 0;
    #pragma unroll
    for (int u = 1; u < 10; u++) if (l >= c_begin[u]) i = u;
    const float* qhp = g_qhf + (size_t)row*AHx;
    const float* ac  = g_acat + cid*AHx;
    const float* as  = g_ascale + i*AHx;
    float acc = 0.f;
    #pragma unroll
    for (int h = lane; h < AHx; h += 32) {
        float xv = qhp[h] + ac[h] + as[h];
        float ge = 0.5f*xv*(1.0f + erff(xv*0.70710678118654752f));
        acc += ge * aW2[h];
    }
    #pragma unroll
    for (int o = 16; o > 0; o >>= 1) acc += __shfl_xor_sync(0xffffffffu, acc, o);
    if (lane == 0) g_alpha[row] = 1.0f/(1.0f + expf(-(acc + ab2[0])));
}

// ---------------- masked softmax + alpha prescale -> tf32 hi planes ----------------
__global__ void __launch_bounds__(256) softmax_kernel()
{
    int w = threadIdx.x >> 5, lane = threadIdx.x & 31;
    int row = blockIdx.x * 8 + w;
    if (row >= NROW) return;
    int l = row % Lx;
    int i = 0;
    #pragma unroll
    for (int u = 1; u < 10; u++) if (l >= c_begin[u]) i = u;
    int nk = (i + 1) * SLOTSx;
    float ls = g_scal[0];
    float a = g_alpha[row];
    #pragma unroll
    for (int s = 0; s < 2; s++) {
        const float* p = (s ? g_lgcf : g_lgsf) + (size_t)row * NKMAX;
        unsigned* q = (s ? g_lgc_h : g_lgs_h) + (size_t)row * NKMAX;
        float wgt = s ? a : (1.0f - a);
        float v[10];
        int cnt = 0;
        float mx = -3.4e38f;
        for (int j = lane; j < nk; j += 32) { float t = p[j]*ls; v[cnt++] = t; mx = fmaxf(mx, t); }
        #pragma unroll
        for (int o = 16; o > 0; o >>= 1) mx = fmaxf(mx, __shfl_xor_sync(0xffffffffu, mx, o));
        float sum = 0.f;
        for (int c2 = 0; c2 < cnt; c2++) { v[c2] = expf(v[c2] - mx); sum += v[c2]; }
        #pragma unroll
        for (int o = 16; o > 0; o >>= 1) sum += __shfl_xor_sync(0xffffffffu, sum, o);
        float inv = wgt / sum;
        cnt = 0;
        for (int j = lane; j < NKMAX; j += 32)
            q[j] = (j < nk) ? to_tf32(v[cnt++] * inv) : 0u;
    }
}

// ---------------- tail ----------------
__global__ void tail_kernel(float* out, int n2, int total) {
    int idx = n2 + blockIdx.x*blockDim.x + threadIdx.x;
    if (idx < total) out[idx] = 0.f;
}

// ---------------- host helpers ----------------
static void launch_gemm(int variant,   // 0: <0,3>  1: <0,1>  2: <1,3>
                        int M, int N, int K,
                        const unsigned* Ah, const unsigned* Al, int lda, long long sA,
                        const unsigned* Bh, const unsigned* Bl, int ldb, long long sB,
                        float* Cf, unsigned* Chi, unsigned* Clo, int ldc, long long sC,
                        const float* bias, const float* gate,
                        int accum, int wr_f32, int wr_split, int batches)
{
    GemmArgs g;
    g.M=M; g.N=N; g.K=K;
    g.Ah=Ah; g.Al=Al; g.lda=lda; g.sA=sA;
    g.Bh=Bh; g.Bl=Bl; g.ldb=ldb; g.sB=sB;
    g.Cf=Cf; g.Chi=Chi; g.Clo=Clo; g.ldc=ldc; g.sC=sC;
    g.bias=bias; g.gate=gate; g.accum=accum; g.wr_f32=wr_f32; g.wr_split=wr_split;
    dim3 grid((N + 127)/128, (M + 127)/128, batches);
    if (variant == 0) {
        int smem = 2 * 2 * (2560 + 2176) * 4;   // 75776
        gemm_tmpl<0,3><<<grid, 256, smem>>>(g);
    } else if (variant == 1) {
        int smem = 2 * 1 * (2560 + 2176) * 4;   // 37888
        gemm_tmpl<0,1><<<grid, 256, smem>>>(g);
    } else {
        int smem = 2 * 2 * (2560 + 2560) * 4;   // 81920
        gemm_tmpl<1,3><<<grid, 256, smem>>>(g);
    }
}

// ---------------- launch ----------------
extern "C" void kernel_launch(void* const* d_in, const int* in_sizes, int n_in,
                              void* d_out, int out_size) {
    const float* x        = (const float*)d_in[0];
    const int*   catids   = (const int*)  d_in[1];
    const float* shmem    = (const float*)d_in[2];
    const float* cat_A    = (const float*)d_in[3];
    const float* cat_B    = (const float*)d_in[4];
    const float* cat_emb  = (const float*)d_in[5];
    const float* scale_emb= (const float*)d_in[6];
    const float* Wq       = (const float*)d_in[7];
    const float* Wk       = (const float*)d_in[8];
    const float* Wv       = (const float*)d_in[9];
    const float* aW1      = (const float*)d_in[10];
    const float* ab1      = (const float*)d_in[11];
    const float* aW2      = (const float*)d_in[12];
    const float* ab2      = (const float*)d_in[13];
    const float* kW1      = (const float*)d_in[14];
    const float* kb1      = (const float*)d_in[15];
    const float* kW2      = (const float*)d_in[16];
    const float* kb2      = (const float*)d_in[17];
    const float* vW1      = (const float*)d_in[18];
    const float* vb1      = (const float*)d_in[19];
    const float* vW2      = (const float*)d_in[20];
    const float* vb2      = (const float*)d_in[21];
    const float* gk       = (const float*)d_in[22];
    const float* gv       = (const float*)d_in[23];
    const float* lt       = (const float*)d_in[24];

    static bool attr_done = false;
    if (!attr_done) {
        cudaFuncSetAttribute(gemm_tmpl<0,3>, cudaFuncAttributeMaxDynamicSharedMemorySize, 75776);
        cudaFuncSetAttribute(gemm_tmpl<0,1>, cudaFuncAttributeMaxDynamicSharedMemorySize, 37888);
        cudaFuncSetAttribute(gemm_tmpl<1,3>, cudaFuncAttributeMaxDynamicSharedMemorySize, 81920);
        attr_done = true;
    }

    #define SYM(p, s) p; cudaGetSymbolAddress((void**)&p, s)
    unsigned* SYM(p_xs_h, g_xs_h);  unsigned* SYM(p_xs_l, g_xs_l);
    unsigned* SYM(p_qs_h, g_qs_h);  unsigned* SYM(p_qs_l, g_qs_l);
    unsigned* SYM(p_Wq_h, g_Wq_h);  unsigned* SYM(p_Wq_l, g_Wq_l);
    unsigned* SYM(p_Wk_h, g_Wk_h);  unsigned* SYM(p_Wk_l, g_Wk_l);
    unsigned* SYM(p_Wv_h, g_Wv_h);  unsigned* SYM(p_Wv_l, g_Wv_l);
    unsigned* SYM(p_aW1_h, g_aW1_h);unsigned* SYM(p_aW1_l, g_aW1_l);
    unsigned* SYM(p_shm_h, g_shm_h);unsigned* SYM(p_shm_l, g_shm_l);
    unsigned* SYM(p_cB_h, g_cB_h);  unsigned* SYM(p_cB_l, g_cB_l);
    unsigned* SYM(p_kW1_h, g_kW1_h);unsigned* SYM(p_kW1_l, g_kW1_l);
    unsigned* SYM(p_kW2_h, g_kW2_h);unsigned* SYM(p_kW2_l, g_kW2_l);
    unsigned* SYM(p_vW1_h, g_vW1_h);unsigned* SYM(p_vW1_l, g_vW1_l);
    unsigned* SYM(p_vW2_h, g_vW2_h);unsigned* SYM(p_vW2_l, g_vW2_l);
    float*    SYM(p_skf, g_skf);    float*    SYM(p_svf, g_svf);
    unsigned* SYM(p_sk_h, g_sk_h);  unsigned* SYM(p_sk_l, g_sk_l);
    unsigned* SYM(p_sv_h, g_sv_h);  unsigned* SYM(p_sv_l, g_sv_l);
    float*    SYM(p_cbkf, g_cbkf);  float*    SYM(p_cbvf, g_cbvf);
    unsigned* SYM(p_kc_h, g_kc_h);  unsigned* SYM(p_kc_l, g_kc_l);
    unsigned* SYM(p_vc_h, g_vc_h);  unsigned* SYM(p_vc_l, g_vc_l);
    float*    SYM(p_lgsf, g_lgsf);  float*    SYM(p_lgcf, g_lgcf);
    unsigned* SYM(p_lgs_h, g_lgs_h);unsigned* SYM(p_lgc_h, g_lgc_h);
    float*    SYM(p_qhf, g_qhf);
    float*    SYM(p_memf, g_memf);
    unsigned* SYM(p_mem_h, g_mem_h);unsigned* SYM(p_mem_l, g_mem_l);
    unsigned* SYM(p_t1k_h, g_t1k_h);unsigned* SYM(p_t1k_l, g_t1k_l);
    unsigned* SYM(p_t1v_h, g_t1v_h);unsigned* SYM(p_t1v_l, g_t1v_l);
    float*    SYM(p_scal, g_scal);
    #undef SYM

    prep_kernel<<<1, 1>>>(gk, gv, lt);

    // -------- split raw inputs --------
    auto split = [&](const float* in, unsigned* h, unsigned* l, long long n) {
        int n4 = (int)(n / 4);
        split_kernel<<<(n4 + 255)/256, 256>>>(in, h, l, n4);
    };
    split(x, p_xs_h, p_xs_l, (long long)NQ);
    split(Wq, p_Wq_h, p_Wq_l, Cx*Cx);
    split(Wk, p_Wk_h, p_Wk_l, Cx*Cx);
    split(Wv, p_Wv_h, p_Wv_l, Cx*Cx);
    split(aW1, p_aW1_h, p_aW1_l, Cx*AHx);             // first Cx rows of aW1
    split(shmem, p_shm_h, p_shm_l, NKMAX*Cx);
    split(cat_B, p_cB_h, p_cB_l, 2560*Cx);
    split(kW1, p_kW1_h, p_kW1_l, Cx*MRx);
    split(kW2, p_kW2_h, p_kW2_l, MRx*Cx);
    split(vW1, p_vW1_h, p_vW1_l, Cx*MRx);
    split(vW2, p_vW2_h, p_vW2_l, MRx*Cx);

    // -------- projections --------
    // query = x @ Wq  -> split only
    launch_gemm(0, NROW, Cx, Cx, p_xs_h, p_xs_l, Cx, 0, p_Wq_h, p_Wq_l, Cx, 0,
                p_memf, p_qs_h, p_qs_l, Cx, 0, nullptr, nullptr, 0, 0, 1, 1);
    // sk = shmem @ Wk -> fp32 + split
    launch_gemm(0, NKMAX, Cx, Cx, p_shm_h, p_shm_l, Cx, 0, p_Wk_h, p_Wk_l, Cx, 0,
                p_skf, p_sk_h, p_sk_l, Cx, 0, nullptr, nullptr, 0, 1, 1, 1);
    // sv = shmem @ Wv -> fp32 + split
    launch_gemm(0, NKMAX, Cx, Cx, p_shm_h, p_shm_l, Cx, 0, p_Wv_h, p_Wv_l, Cx, 0,
                p_svf, p_sv_h, p_sv_l, Cx, 0, nullptr, nullptr, 0, 1, 1, 1);
    // cbk / cbv -> fp32 only
    launch_gemm(0, 2560, Cx, Cx, p_cB_h, p_cB_l, Cx, 0, p_Wk_h, p_Wk_l, Cx, 0,
                p_cbkf, p_kc_h, p_kc_l, Cx, 0, nullptr, nullptr, 0, 1, 0, 1);
    launch_gemm(0, 2560, Cx, Cx, p_cB_h, p_cB_l, Cx, 0, p_Wv_h, p_Wv_l, Cx, 0,
                p_cbvf, p_kc_h, p_kc_l, Cx, 0, nullptr, nullptr, 0, 1, 0, 1);
    // qh = query @ aW1[:Cx]  (1-pass)
    launch_gemm(1, NROW, AHx, Cx, p_qs_h, nullptr, Cx, 0, p_aW1_h, nullptr, AHx, 0,
                p_qhf, p_t1k_h, p_t1k_l, AHx, 0, nullptr, nullptr, 0, 1, 0, 1);

    // per-batch kc/vc (reads fp32, writes split)
    kcvc_kernel<<<Bx*NKMAX, 256>>>(catids, cat_A);
    // alpha constants + per-row alpha
    aconst_kernel<<<NCATx + Sx, AHx>>>(cat_emb, scale_emb, aW1, ab1);
    alpha_kernel<<<(NROW + 7)/8, 256>>>(catids, aW2, ab2);

    // -------- logits (transB, 3-pass) --------
    launch_gemm(2, NROW, NKMAX, Cx, p_qs_h, p_qs_l, Cx, 0, p_sk_h, p_sk_l, Cx, 0,
                p_lgsf, p_lgs_h, p_lgc_h, NKMAX, 0, nullptr, nullptr, 0, 1, 0, 1);
    launch_gemm(2, Lx, NKMAX, Cx, p_qs_h, p_qs_l, Cx, (long long)Lx*Cx,
                p_kc_h, p_kc_l, Cx, (long long)NKMAX*Cx,
                p_lgcf, p_lgs_h, p_lgc_h, NKMAX, (long long)Lx*NKMAX, nullptr, nullptr, 0, 1, 0, Bx);

    // masked softmax -> tf32 hi planes (prescaled by (1-a)/a)
    softmax_kernel<<<(NROW + 7)/8, 256>>>();

    // -------- PV (1-pass) --------
    // memf = P_s @ sv
    launch_gemm(1, NROW, Cx, NKMAX, p_lgs_h, nullptr, NKMAX, 0, p_sv_h, nullptr, Cx, 0,
                p_memf, p_mem_h, p_mem_l, Cx, 0, nullptr, nullptr, 0, 1, 0, 1);
    // mem = memf + P_c @ vc   -> split planes
    launch_gemm(1, Lx, Cx, NKMAX, p_lgc_h, nullptr, NKMAX, (long long)Lx*NKMAX,
                p_vc_h, nullptr, Cx, (long long)NKMAX*Cx,
                p_memf, p_mem_h, p_mem_l, Cx, (long long)Lx*Cx, nullptr, nullptr, 1, 0, 1, Bx);

    // -------- heads (3-pass) --------
    launch_gemm(0, NROW, MRx, Cx, p_mem_h, p_mem_l, Cx, 0, p_kW1_h, p_kW1_l, MRx, 0,
                p_memf, p_t1k_h, p_t1k_l, MRx, 0, kb1, nullptr, 0, 0, 1, 1);
    launch_gemm(0, NROW, MRx, Cx, p_mem_h, p_mem_l, Cx, 0, p_vW1_h, p_vW1_l, MRx, 0,
                p_memf, p_t1v_h, p_t1v_l, MRx, 0, vb1, nullptr, 0, 0, 1, 1);

    float* outk = (float*)d_out;
    float* outv = (float*)d_out + (size_t)NROW * Cx;
    launch_gemm(0, NROW, Cx, MRx, p_t1k_h, p_t1k_l, MRx, 0, p_kW2_h, p_kW2_l, Cx, 0,
                outk, p_mem_h, p_mem_l, Cx, 0, kb2, p_scal + 1, 0, 1, 0, 1);
    launch_gemm(0, NROW, Cx, MRx, p_t1v_h, p_t1v_l, MRx, 0, p_vW2_h, p_vW2_l, Cx, 0,
                outv, p_mem_h, p_mem_l, Cx, 0, vb2, p_scal + 2, 0, 1, 0, 1);

    tail_kernel<<<1, 256>>>((float*)d_out, 2 * NROW * Cx, out_size);
}

// round 4
// speedup vs baseline: 4.5137x; 1.0657x over previous
#include <cuda_runtime.h>
#include <math.h>

// ---------------- problem constants ----------------
static constexpr int Bx = 32, Lx = 680, Cx = 1024;
static constexpr int Sx = 10, SLOTSx = 32, Rx = 8, NCATx = 22;
static constexpr int MRx = 64, AHx = 128;
static constexpr int NROW = Bx * Lx;            // 21760
static constexpr int NKMAX = Sx * SLOTSx;       // 320
static constexpr int NQ = NROW * Cx;            // 22282240

__constant__ int c_begin[10] = {0,1,5,14,30,55,91,155,255,424};

// ---------------- device scratch ----------------
__device__ unsigned g_xs_h[NQ], g_xs_l[NQ];
__device__ unsigned g_qs_h[NQ], g_qs_l[NQ];
__device__ unsigned g_WqT_h[Cx*Cx], g_WqT_l[Cx*Cx];
__device__ unsigned g_WkT_h[Cx*Cx], g_WkT_l[Cx*Cx];
__device__ unsigned g_WvT_h[Cx*Cx], g_WvT_l[Cx*Cx];
__device__ unsigned g_aW1T_h[AHx*Cx], g_aW1T_l[AHx*Cx];
__device__ unsigned g_w1T_h[(2*MRx)*Cx], g_w1T_l[(2*MRx)*Cx];   // [128][1024] kW1^T | vW1^T
__device__ unsigned g_kW2T_h[Cx*MRx], g_kW2T_l[Cx*MRx];
__device__ unsigned g_vW2T_h[Cx*MRx], g_vW2T_l[Cx*MRx];
__device__ unsigned g_shm_h[NKMAX*Cx], g_shm_l[NKMAX*Cx];
__device__ unsigned g_cB_h[2560*Cx], g_cB_l[2560*Cx];

__device__ float    g_skf[NKMAX*Cx];
__device__ unsigned g_sk_h[NKMAX*Cx], g_sk_l[NKMAX*Cx];
__device__ float    g_svf[NKMAX*Cx];
__device__ unsigned g_svT_h[Cx*NKMAX], g_svT_l[Cx*NKMAX];
__device__ float    g_cbkf[2560*Cx], g_cbvf[2560*Cx];
__device__ unsigned g_kc_h[Bx*NKMAX*Cx], g_kc_l[Bx*NKMAX*Cx];
__device__ float    g_vcf[Bx*NKMAX*Cx];
__device__ unsigned g_vcT_h[Bx*Cx*NKMAX], g_vcT_l[Bx*Cx*NKMAX];
__device__ float    g_lgsf[NROW*NKMAX], g_lgcf[NROW*NKMAX];
__device__ unsigned g_lgs_h[NROW*NKMAX], g_lgc_h[NROW*NKMAX];
__device__ float    g_qhf[NROW*AHx];
__device__ float    g_memf[NQ];
__device__ unsigned g_mem_h[NQ], g_mem_l[NQ];
__device__ unsigned g_t1_h[NROW*(2*MRx)], g_t1_l[NROW*(2*MRx)];
__device__ float    g_acat[NCATx*AHx];
__device__ float    g_ascale[Sx*AHx];
__device__ float    g_alpha[NROW];
__device__ float    g_scal[4];
__device__ float    g_bias1[2*MRx];

// ---------------- helpers ----------------
__device__ __forceinline__ void split_tf32(float x, unsigned& hi, unsigned& lo) {
    unsigned h; asm("cvt.rna.tf32.f32 %0, %1;" : "=r"(h) : "f"(x));
    float hf = __uint_as_float(h);
    unsigned l; asm("cvt.rna.tf32.f32 %0, %1;" : "=r"(l) : "f"(x - hf));
    hi = h; lo = l;
}
__device__ __forceinline__ unsigned to_tf32(float x) {
    unsigned h; asm("cvt.rna.tf32.f32 %0, %1;" : "=r"(h) : "f"(x)); return h;
}
__device__ __forceinline__ void mma8(float* d, const unsigned* a, const unsigned* b) {
    asm volatile(
        "mma.sync.aligned.m16n8k8.row.col.f32.tf32.tf32.f32 "
        "{%0,%1,%2,%3}, {%4,%5,%6,%7}, {%8,%9}, {%0,%1,%2,%3};"
        : "+f"(d[0]), "+f"(d[1]), "+f"(d[2]), "+f"(d[3])
        : "r"(a[0]), "r"(a[1]), "r"(a[2]), "r"(a[3]), "r"(b[0]), "r"(b[1]));
}
__device__ __forceinline__ uint4 ldsm4(unsigned a) {
    uint4 r;
    asm volatile("ldmatrix.sync.aligned.m8n8.x4.shared.b16 {%0,%1,%2,%3}, [%4];"
        : "=r"(r.x), "=r"(r.y), "=r"(r.z), "=r"(r.w) : "r"(a));
    return r;
}
__device__ __forceinline__ unsigned smaddr(const void* p) {
    unsigned a;
    asm("{.reg .u64 u; cvta.to.shared.u64 u, %1; cvt.u32.u64 %0, u;}" : "=r"(a) : "l"(p));
    return a;
}
__device__ __forceinline__ void cp16(unsigned dst, const void* src, bool ok) {
    int sz = ok ? 16 : 0;
    asm volatile("cp.async.cg.shared.global [%0], [%1], 16, %2;\n" :: "r"(dst), "l"(src), "r"(sz));
}
__device__ __forceinline__ void cp_commit() { asm volatile("cp.async.commit_group;"); }
template<int N> __device__ __forceinline__ void cp_wait() {
    asm volatile("cp.async.wait_group %0;" :: "n"(N));
}

// ---------------- prep ----------------
__global__ void prep_kernel(const float* gk, const float* gv, const float* lt) {
    float temp = expf(lt[0]);
    temp = fminf(fmaxf(temp, 0.05f), 1.0f);
    g_scal[0] = (1.0f / 32.0f) / temp;
    g_scal[1] = 1.0f / (1.0f + expf(-gk[0]));
    g_scal[2] = 1.0f / (1.0f + expf(-gv[0]));
}

// ---------------- split row-major fp32 -> hi/lo planes ----------------
__global__ void split_kernel(const float* __restrict__ in, unsigned* __restrict__ hi,
                             unsigned* __restrict__ lo, int n4) {
    int i = blockIdx.x * 256 + threadIdx.x;
    if (i >= n4) return;
    float4 v = ((const float4*)in)[i];
    uint4 h, l;
    split_tf32(v.x, h.x, l.x); split_tf32(v.y, h.y, l.y);
    split_tf32(v.z, h.z, l.z); split_tf32(v.w, h.w, l.w);
    ((uint4*)hi)[i] = h; ((uint4*)lo)[i] = l;
}

// ---------------- transpose + split: in [R][C] -> out planes [C][R] ----------------
__global__ void tsplit_kernel(const float* __restrict__ in, int R, int C, long long sIn,
                              unsigned* __restrict__ oh, unsigned* __restrict__ ol, long long sOut)
{
    __shared__ float t[32][33];
    in += (size_t)blockIdx.z * sIn;
    oh += (size_t)blockIdx.z * sOut;
    ol += (size_t)blockIdx.z * sOut;
    int r0 = blockIdx.y * 32, c0 = blockIdx.x * 32;
    int tx = threadIdx.x, ty = threadIdx.y;
    #pragma unroll
    for (int i = 0; i < 32; i += 8) {
        int r = r0 + ty + i;
        t[ty + i][tx] = (r < R && c0 + tx < C) ? in[(size_t)r * C + c0 + tx] : 0.f;
    }
    __syncthreads();
    #pragma unroll
    for (int i = 0; i < 32; i += 8) {
        int c = c0 + ty + i, r = r0 + tx;
        if (c < C && r < R) {
            unsigned h, l; split_tf32(t[tx][ty + i], h, l);
            oh[(size_t)c * R + r] = h;
            ol[(size_t)c * R + r] = l;
        }
    }
}

// ---------------- GEMM args ----------------
struct GemmArgs {
    int M, N, K;
    const unsigned *Ah, *Al; int lda; long long sA;
    const unsigned *Bh, *Bl; int ldb; long long sB;   // B is [N][K] (NT)
    float* Cf; unsigned *Chi, *Clo; int ldc; long long sC;
    const float* bias; const float* gate;
    int accum, wr_f32, wr_split;
};

// ---------------- NT TF32 GEMM with ldmatrix fragments ----------------
template<int NPASS>
__global__ void __launch_bounds__(256, 2) gemm_tmpl(GemmArgs g)
{
    constexpr int AW  = 20;                // padded row stride (words)
    constexpr int ASZ = 128 * AW;          // 2560 words per plane tile
    constexpr int NPL = (NPASS == 3) ? 2 : 1;
    constexpr int STG = NPL * 2 * ASZ;     // words per stage (A planes + B planes)
    extern __shared__ unsigned sm[];

    const int tid = threadIdx.x, lane = tid & 31, wid = tid >> 5;
    const int wm = wid >> 2, wn = wid & 3, tg = lane & 3, gid = lane >> 2;
    const int bm = blockIdx.y * 128, bn = blockIdx.x * 128;
    const long long z = blockIdx.z;

    const unsigned* Ap[2];
    Ap[0] = g.Ah + z * g.sA;
    Ap[1] = (NPASS == 3) ? g.Al + z * g.sA : Ap[0];
    const unsigned* Bp[2];
    Bp[0] = g.Bh + z * g.sB;
    Bp[1] = (NPASS == 3) ? g.Bl + z * g.sB : Bp[0];

    const unsigned smbase = smaddr(sm);

    // ldmatrix per-thread base addresses
    const int am = lane >> 3;
    const int a_row = (am & 1) * 8 + (lane & 7);
    const int a_kw  = (am >> 1) * 4;
    const int b_row = (am >> 1) * 8 + (lane & 7);
    const int b_kw  = (am & 1) * 4;
    unsigned aA[4], bA[2];
    #pragma unroll
    for (int mt = 0; mt < 4; mt++)
        aA[mt] = smbase + (unsigned)((wm*64 + mt*16 + a_row) * AW + a_kw) * 4u;
    #pragma unroll
    for (int pr = 0; pr < 2; pr++)
        bA[pr] = smbase + (unsigned)(NPL * ASZ) * 4u
               + (unsigned)((wn*32 + pr*16 + b_row) * AW + b_kw) * 4u;

    float acc[4][4][4];
    #pragma unroll
    for (int mt = 0; mt < 4; mt++)
        #pragma unroll
        for (int nt = 0; nt < 4; nt++)
            #pragma unroll
            for (int u = 0; u < 4; u++) acc[mt][nt][u] = 0.f;

    auto load_stage = [&](int s, int k0) {
        unsigned base = smbase + (unsigned)(s * STG) * 4u;
        #pragma unroll
        for (int i = 0; i < 2 * NPL; i++) {
            int c = tid + i * 256;
            int p = c >> 9, rem = c & 511;
            int row = rem >> 2, kc = (rem & 3) * 4;
            bool ok = (bm + row) < g.M;
            const unsigned* src = ok ? Ap[p] + (size_t)(bm + row) * g.lda + k0 + kc : Ap[p];
            cp16(base + (unsigned)(p * ASZ + row * AW + kc) * 4u, src, ok);
        }
        unsigned bbase = base + (unsigned)(NPL * ASZ) * 4u;
        #pragma unroll
        for (int i = 0; i < 2 * NPL; i++) {
            int c = tid + i * 256;
            int p = c >> 9, rem = c & 511;
            int row = rem >> 2, kc = (rem & 3) * 4;
            bool ok = (bn + row) < g.N;
            const unsigned* src = ok ? Bp[p] + (size_t)(bn + row) * g.ldb + k0 + kc : Bp[p];
            cp16(bbase + (unsigned)(p * ASZ + row * AW + kc) * 4u, src, ok);
        }
    };

    auto compute = [&](int s) {
        const unsigned so = (unsigned)(s * STG) * 4u;
        #pragma unroll
        for (int kk = 0; kk < 16; kk += 8) {
            const unsigned kb = so + (unsigned)kk * 4u;
            unsigned bh[4][2], bl[4][2];
            #pragma unroll
            for (int pr = 0; pr < 2; pr++) {
                uint4 r = ldsm4(bA[pr] + kb);
                bh[pr*2+0][0] = r.x; bh[pr*2+0][1] = r.y;
                bh[pr*2+1][0] = r.z; bh[pr*2+1][1] = r.w;
                if (NPASS == 3) {
                    uint4 q = ldsm4(bA[pr] + kb + (unsigned)ASZ * 4u);
                    bl[pr*2+0][0] = q.x; bl[pr*2+0][1] = q.y;
                    bl[pr*2+1][0] = q.z; bl[pr*2+1][1] = q.w;
                }
            }
            #pragma unroll
            for (int mt = 0; mt < 4; mt++) {
                uint4 ah4 = ldsm4(aA[mt] + kb);
                uint4 al4 = make_uint4(0,0,0,0);
                if (NPASS == 3) al4 = ldsm4(aA[mt] + kb + (unsigned)ASZ * 4u);
                #pragma unroll
                for (int nt = 0; nt < 4; nt++) {
                    mma8(acc[mt][nt], (const unsigned*)&ah4, bh[nt]);
                    if (NPASS == 3) {
                        mma8(acc[mt][nt], (const unsigned*)&ah4, bl[nt]);
                        mma8(acc[mt][nt], (const unsigned*)&al4, bh[nt]);
                    }
                }
            }
        }
    };

    const int nK = g.K >> 4;
    load_stage(0, 0);
    cp_commit();
    for (int kt = 0; kt < nK; kt++) {
        if (kt + 1 < nK) {
            load_stage((kt + 1) & 1, (kt + 1) << 4);
            cp_commit();
            cp_wait<1>();
        } else {
            cp_wait<0>();
        }
        __syncthreads();
        compute(kt & 1);
        __syncthreads();
    }

    // ---------------- epilogue ----------------
    const float gt = g.gate ? *g.gate : 1.0f;
    float* Cf = g.Cf + z * g.sC;
    unsigned* Chi = g.Chi + z * g.sC;
    unsigned* Clo = g.Clo + z * g.sC;
    #pragma unroll
    for (int mt = 0; mt < 4; mt++) {
        int r0 = bm + wm * 64 + mt * 16 + gid;
        int r1 = r0 + 8;
        #pragma unroll
        for (int nt = 0; nt < 4; nt++) {
            int col = bn + wn * 32 + nt * 8 + 2 * tg;
            if (col >= g.N) continue;
            float b0 = g.bias ? g.bias[col]     : 0.f;
            float b1 = g.bias ? g.bias[col + 1] : 0.f;
            #pragma unroll
            for (int half = 0; half < 2; half++) {
                int r = half ? r1 : r0;
                if (r >= g.M) continue;
                size_t o = (size_t)r * g.ldc + col;
                float v0 = gt * (acc[mt][nt][half*2+0] + b0);
                float v1 = gt * (acc[mt][nt][half*2+1] + b1);
                if (g.accum) { v0 += Cf[o]; v1 += Cf[o+1]; }
                if (g.wr_f32) *(float2*)(Cf + o) = make_float2(v0, v1);
                if (g.wr_split) {
                    unsigned h0,l0,h1,l1;
                    split_tf32(v0, h0, l0); split_tf32(v1, h1, l1);
                    Chi[o] = h0; Chi[o+1] = h1;
                    Clo[o] = l0; Clo[o+1] = l1;
                }
            }
        }
    }
}

// ---------------- kc (split) / vc (fp32) ----------------
__global__ void __launch_bounds__(256) kcvc_kernel(const int* __restrict__ catids,
                                                   const float* __restrict__ cat_A)
{
    int blk = blockIdx.x;
    int b = blk / 320, rem = blk % 320;
    int v = rem >> 5, s = rem & 31;
    int cid = catids[b]; if (cid < 0) cid = 0;
    float a[Rx];
    #pragma unroll
    for (int r = 0; r < Rx; r++) a[r] = cat_A[(cid*Sx + v)*Rx + r];
    int c = threadIdx.x * 4;
    size_t base_sc = ((size_t)(v*SLOTSx + s))*Cx + c;
    float4 ka = *(const float4*)(g_skf + base_sc);
    float4 va = *(const float4*)(g_svf + base_sc);
    #pragma unroll
    for (int r = 0; r < Rx; r++) {
        size_t idx = ((size_t)((v*Rx + r)*SLOTSx + s))*Cx + c;
        float4 kb = *(const float4*)(g_cbkf + idx);
        float4 vb = *(const float4*)(g_cbvf + idx);
        ka.x += a[r]*kb.x; ka.y += a[r]*kb.y; ka.z += a[r]*kb.z; ka.w += a[r]*kb.w;
        va.x += a[r]*vb.x; va.y += a[r]*vb.y; va.z += a[r]*vb.z; va.w += a[r]*vb.w;
    }
    size_t o = ((size_t)(b*320 + v*SLOTSx + s))*Cx + c;
    uint4 h, l;
    split_tf32(ka.x,h.x,l.x); split_tf32(ka.y,h.y,l.y); split_tf32(ka.z,h.z,l.z); split_tf32(ka.w,h.w,l.w);
    *(uint4*)(g_kc_h + o) = h; *(uint4*)(g_kc_l + o) = l;
    *(float4*)(g_vcf + o) = va;
}

// ---------------- alpha constant tables ----------------
__global__ void aconst_kernel(const float* __restrict__ cat_emb,
                              const float* __restrict__ scale_emb,
                              const float* __restrict__ aW1,
                              const float* __restrict__ ab1)
{
    int idx = blockIdx.x;
    int h = threadIdx.x;
    if (idx < NCATx) {
        float acc = 0.f;
        const float* ce = cat_emb + (size_t)idx * Cx;
        for (int c = 0; c < Cx; c++)
            acc += ce[c] * aW1[(size_t)(Cx + c)*AHx + h];
        g_acat[idx*AHx + h] = acc;
    } else {
        int i = idx - NCATx;
        float acc = ab1[h];
        const float* se = scale_emb + (size_t)i * Cx;
        for (int c = 0; c < Cx; c++)
            acc += se[c] * aW1[(size_t)(2*Cx + c)*AHx + h];
        g_ascale[i*AHx + h] = acc;
    }
}

// ---------------- alpha gate per row ----------------
__global__ void __launch_bounds__(256) alpha_kernel(const int* __restrict__ catids,
                                                    const float* __restrict__ aW2,
                                                    const float* __restrict__ ab2)
{
    int w = threadIdx.x >> 5, lane = threadIdx.x & 31;
    int row = blockIdx.x * 8 + w;
    if (row >= NROW) return;
    int b = row / Lx, l = row % Lx;
    int cid = catids[b];
    if (cid < 0) { if (lane == 0) g_alpha[row] = 0.f; return; }
    int i = 0;
    #pragma unroll
    for (int u = 1; u < 10; u++) if (l >= c_begin[u]) i = u;
    const float* qhp = g_qhf + (size_t)row*AHx;
    const float* ac  = g_acat + cid*AHx;
    const float* as  = g_ascale + i*AHx;
    float acc = 0.f;
    #pragma unroll
    for (int h = lane; h < AHx; h += 32) {
        float xv = qhp[h] + ac[h] + as[h];
        float ge = 0.5f*xv*(1.0f + erff(xv*0.70710678118654752f));
        acc += ge * aW2[h];
    }
    #pragma unroll
    for (int o = 16; o > 0; o >>= 1) acc += __shfl_xor_sync(0xffffffffu, acc, o);
    if (lane == 0) g_alpha[row] = 1.0f/(1.0f + expf(-(acc + ab2[0])));
}

// ---------------- masked softmax + alpha prescale -> tf32 hi planes ----------------
__global__ void __launch_bounds__(256) softmax_kernel()
{
    int w = threadIdx.x >> 5, lane = threadIdx.x & 31;
    int row = blockIdx.x * 8 + w;
    if (row >= NROW) return;
    int l = row % Lx;
    int i = 0;
    #pragma unroll
    for (int u = 1; u < 10; u++) if (l >= c_begin[u]) i = u;
    int nk = (i + 1) * SLOTSx;
    float ls = g_scal[0];
    float a = g_alpha[row];
    #pragma unroll
    for (int s = 0; s < 2; s++) {
        const float* p = (s ? g_lgcf : g_lgsf) + (size_t)row * NKMAX;
        unsigned* q = (s ? g_lgc_h : g_lgs_h) + (size_t)row * NKMAX;
        float wgt = s ? a : (1.0f - a);
        float v[10];
        int cnt = 0;
        float mx = -3.4e38f;
        for (int j = lane; j < nk; j += 32) { float t = p[j]*ls; v[cnt++] = t; mx = fmaxf(mx, t); }
        #pragma unroll
        for (int o = 16; o > 0; o >>= 1) mx = fmaxf(mx, __shfl_xor_sync(0xffffffffu, mx, o));
        float sum = 0.f;
        for (int c2 = 0; c2 < cnt; c2++) { v[c2] = expf(v[c2] - mx); sum += v[c2]; }
        #pragma unroll
        for (int o = 16; o > 0; o >>= 1) sum += __shfl_xor_sync(0xffffffffu, sum, o);
        float inv = wgt / sum;
        cnt = 0;
        for (int j = lane; j < NKMAX; j += 32)
            q[j] = (j < nk) ? to_tf32(v[cnt++] * inv) : 0u;
    }
}

// ---------------- tail ----------------
__global__ void tail_kernel(float* out, int n2, int total) {
    int idx = n2 + blockIdx.x*blockDim.x + threadIdx.x;
    if (idx < total) out[idx] = 0.f;
}

// ---------------- host helpers ----------------
static void launch_gemm(int npass, int M, int N, int K,
                        const unsigned* Ah, const unsigned* Al, int lda, long long sA,
                        const unsigned* Bh, const unsigned* Bl, int ldb, long long sB,
                        float* Cf, unsigned* Chi, unsigned* Clo, int ldc, long long sC,
                        const float* bias, const float* gate,
                        int accum, int wr_f32, int wr_split, int batches)
{
    GemmArgs g;
    g.M=M; g.N=N; g.K=K;
    g.Ah=Ah; g.Al=Al; g.lda=lda; g.sA=sA;
    g.Bh=Bh; g.Bl=Bl; g.ldb=ldb; g.sB=sB;
    g.Cf=Cf; g.Chi=Chi; g.Clo=Clo; g.ldc=ldc; g.sC=sC;
    g.bias=bias; g.gate=gate; g.accum=accum; g.wr_f32=wr_f32; g.wr_split=wr_split;
    dim3 grid((N + 127)/128, (M + 127)/128, batches);
    if (npass == 3) gemm_tmpl<3><<<grid, 256, 81920>>>(g);
    else            gemm_tmpl<1><<<grid, 256, 40960>>>(g);
}

static void launch_tsplit(const float* in, int R, int C, long long sIn,
                          unsigned* oh, unsigned* ol, long long sOut, int batches)
{
    dim3 grid((C + 31)/32, (R + 31)/32, batches);
    tsplit_kernel<<<grid, dim3(32, 8)>>>(in, R, C, sIn, oh, ol, sOut);
}

// ---------------- launch ----------------
extern "C" void kernel_launch(void* const* d_in, const int* in_sizes, int n_in,
                              void* d_out, int out_size) {
    const float* x        = (const float*)d_in[0];
    const int*   catids   = (const int*)  d_in[1];
    const float* shmem    = (const float*)d_in[2];
    const float* cat_A    = (const float*)d_in[3];
    const float* cat_B    = (const float*)d_in[4];
    const float* cat_emb  = (const float*)d_in[5];
    const float* scale_emb= (const float*)d_in[6];
    const float* Wq       = (const float*)d_in[7];
    const float* Wk       = (const float*)d_in[8];
    const float* Wv       = (const float*)d_in[9];
    const float* aW1      = (const float*)d_in[10];
    const float* ab1      = (const float*)d_in[11];
    const float* aW2      = (const float*)d_in[12];
    const float* ab2      = (const float*)d_in[13];
    const float* kW1      = (const float*)d_in[14];
    const float* kb1      = (const float*)d_in[15];
    const float* kW2      = (const float*)d_in[16];
    const float* kb2      = (const float*)d_in[17];
    const float* vW1      = (const float*)d_in[18];
    const float* vb1      = (const float*)d_in[19];
    const float* vW2      = (const float*)d_in[20];
    const float* vb2      = (const float*)d_in[21];
    const float* gk       = (const float*)d_in[22];
    const float* gv       = (const float*)d_in[23];
    const float* lt       = (const float*)d_in[24];

    cudaFuncSetAttribute(gemm_tmpl<3>, cudaFuncAttributeMaxDynamicSharedMemorySize, 81920);
    cudaFuncSetAttribute(gemm_tmpl<1>, cudaFuncAttributeMaxDynamicSharedMemorySize, 40960);

    #define SYM(t, p, s) t p; cudaGetSymbolAddress((void**)&p, s)
    SYM(unsigned*, p_xs_h, g_xs_h);   SYM(unsigned*, p_xs_l, g_xs_l);
    SYM(unsigned*, p_qs_h, g_qs_h);   SYM(unsigned*, p_qs_l, g_qs_l);
    SYM(unsigned*, p_WqT_h, g_WqT_h); SYM(unsigned*, p_WqT_l, g_WqT_l);
    SYM(unsigned*, p_WkT_h, g_WkT_h); SYM(unsigned*, p_WkT_l, g_WkT_l);
    SYM(unsigned*, p_WvT_h, g_WvT_h); SYM(unsigned*, p_WvT_l, g_WvT_l);
    SYM(unsigned*, p_aW1T_h, g_aW1T_h); SYM(unsigned*, p_aW1T_l, g_aW1T_l);
    SYM(unsigned*, p_w1T_h, g_w1T_h); SYM(unsigned*, p_w1T_l, g_w1T_l);
    SYM(unsigned*, p_kW2T_h, g_kW2T_h); SYM(unsigned*, p_kW2T_l, g_kW2T_l);
    SYM(unsigned*, p_vW2T_h, g_vW2T_h); SYM(unsigned*, p_vW2T_l, g_vW2T_l);
    SYM(unsigned*, p_shm_h, g_shm_h); SYM(unsigned*, p_shm_l, g_shm_l);
    SYM(unsigned*, p_cB_h, g_cB_h);   SYM(unsigned*, p_cB_l, g_cB_l);
    SYM(float*,    p_skf, g_skf);
    SYM(unsigned*, p_sk_h, g_sk_h);   SYM(unsigned*, p_sk_l, g_sk_l);
    SYM(float*,    p_svf, g_svf);
    SYM(unsigned*, p_svT_h, g_svT_h); SYM(unsigned*, p_svT_l, g_svT_l);
    SYM(float*,    p_cbkf, g_cbkf);   SYM(float*,    p_cbvf, g_cbvf);
    SYM(unsigned*, p_kc_h, g_kc_h);   SYM(unsigned*, p_kc_l, g_kc_l);
    SYM(float*,    p_vcf, g_vcf);
    SYM(unsigned*, p_vcT_h, g_vcT_h); SYM(unsigned*, p_vcT_l, g_vcT_l);
    SYM(float*,    p_lgsf, g_lgsf);   SYM(float*,    p_lgcf, g_lgcf);
    SYM(unsigned*, p_lgs_h, g_lgs_h); SYM(unsigned*, p_lgc_h, g_lgc_h);
    SYM(float*,    p_qhf, g_qhf);
    SYM(float*,    p_memf, g_memf);
    SYM(unsigned*, p_mem_h, g_mem_h); SYM(unsigned*, p_mem_l, g_mem_l);
    SYM(unsigned*, p_t1_h, g_t1_h);   SYM(unsigned*, p_t1_l, g_t1_l);
    SYM(float*,    p_scal, g_scal);
    SYM(float*,    p_bias1, g_bias1);
    #undef SYM

    prep_kernel<<<1, 1>>>(gk, gv, lt);

    // -------- operand preparation --------
    // A-side splits (row-major)
    split_kernel<<<(NQ/4 + 255)/256, 256>>>(x, p_xs_h, p_xs_l, NQ/4);
    split_kernel<<<(NKMAX*Cx/4 + 255)/256, 256>>>(shmem, p_shm_h, p_shm_l, NKMAX*Cx/4);
    split_kernel<<<(2560*Cx/4 + 255)/256, 256>>>(cat_B, p_cB_h, p_cB_l, 2560*Cx/4);
    // B-side transposes (weights -> [n][k] planes)
    launch_tsplit(Wq, Cx, Cx, 0, p_WqT_h, p_WqT_l, 0, 1);
    launch_tsplit(Wk, Cx, Cx, 0, p_WkT_h, p_WkT_l, 0, 1);
    launch_tsplit(Wv, Cx, Cx, 0, p_WvT_h, p_WvT_l, 0, 1);
    launch_tsplit(aW1, Cx, AHx, 0, p_aW1T_h, p_aW1T_l, 0, 1);       // first Cx rows
    launch_tsplit(kW1, Cx, MRx, 0, p_w1T_h, p_w1T_l, 0, 1);          // rows 0..63
    launch_tsplit(vW1, Cx, MRx, 0, p_w1T_h + MRx*Cx, p_w1T_l + MRx*Cx, 0, 1);  // rows 64..127
    launch_tsplit(kW2, MRx, Cx, 0, p_kW2T_h, p_kW2T_l, 0, 1);
    launch_tsplit(vW2, MRx, Cx, 0, p_vW2T_h, p_vW2T_l, 0, 1);
    // bias concat kb1|vb1
    cudaMemcpyAsync(p_bias1, kb1, MRx*sizeof(float), cudaMemcpyDeviceToDevice);
    cudaMemcpyAsync(p_bias1 + MRx, vb1, MRx*sizeof(float), cudaMemcpyDeviceToDevice);

    // -------- projections --------
    launch_gemm(3, NROW, Cx, Cx, p_xs_h, p_xs_l, Cx, 0, p_WqT_h, p_WqT_l, Cx, 0,
                p_memf, p_qs_h, p_qs_l, Cx, 0, nullptr, nullptr, 0, 0, 1, 1);
    launch_gemm(3, NKMAX, Cx, Cx, p_shm_h, p_shm_l, Cx, 0, p_WkT_h, p_WkT_l, Cx, 0,
                p_skf, p_sk_h, p_sk_l, Cx, 0, nullptr, nullptr, 0, 1, 1, 1);
    launch_gemm(3, NKMAX, Cx, Cx, p_shm_h, p_shm_l, Cx, 0, p_WvT_h, p_WvT_l, Cx, 0,
                p_svf, p_sk_h, p_sk_l, Cx, 0, nullptr, nullptr, 0, 1, 0, 1);
    launch_gemm(3, 2560, Cx, Cx, p_cB_h, p_cB_l, Cx, 0, p_WkT_h, p_WkT_l, Cx, 0,
                p_cbkf, p_kc_h, p_kc_l, Cx, 0, nullptr, nullptr, 0, 1, 0, 1);
    launch_gemm(3, 2560, Cx, Cx, p_cB_h, p_cB_l, Cx, 0, p_WvT_h, p_WvT_l, Cx, 0,
                p_cbvf, p_kc_h, p_kc_l, Cx, 0, nullptr, nullptr, 0, 1, 0, 1);
    // qh = query @ aW1[:Cx]  (1-pass)
    launch_gemm(1, NROW, AHx, Cx, p_qs_h, nullptr, Cx, 0, p_aW1T_h, nullptr, Cx, 0,
                p_qhf, p_t1_h, p_t1_l, AHx, 0, nullptr, nullptr, 0, 1, 0, 1);

    // sv^T for PV
    launch_tsplit(p_svf, NKMAX, Cx, 0, p_svT_h, p_svT_l, 0, 1);

    // per-batch kc (split) + vc (fp32), then vc^T
    kcvc_kernel<<<Bx*NKMAX, 256>>>(catids, cat_A);
    launch_tsplit(p_vcf, NKMAX, Cx, (long long)NKMAX*Cx, p_vcT_h, p_vcT_l, (long long)Cx*NKMAX, Bx);

    // alpha constants + per-row alpha
    aconst_kernel<<<NCATx + Sx, AHx>>>(cat_emb, scale_emb, aW1, ab1);
    alpha_kernel<<<(NROW + 7)/8, 256>>>(catids, aW2, ab2);

    // -------- logits (3-pass) --------
    launch_gemm(3, NROW, NKMAX, Cx, p_qs_h, p_qs_l, Cx, 0, p_sk_h, p_sk_l, Cx, 0,
                p_lgsf, p_lgs_h, p_lgc_h, NKMAX, 0, nullptr, nullptr, 0, 1, 0, 1);
    launch_gemm(3, Lx, NKMAX, Cx, p_qs_h, p_qs_l, Cx, (long long)Lx*Cx,
                p_kc_h, p_kc_l, Cx, (long long)NKMAX*Cx,
                p_lgcf, p_lgs_h, p_lgc_h, NKMAX, (long long)Lx*NKMAX, nullptr, nullptr, 0, 1, 0, Bx);

    // masked softmax -> tf32 hi planes (prescaled by (1-a)/a)
    softmax_kernel<<<(NROW + 7)/8, 256>>>();

    // -------- PV (1-pass) --------
    launch_gemm(1, NROW, Cx, NKMAX, p_lgs_h, nullptr, NKMAX, 0, p_svT_h, nullptr, NKMAX, 0,
                p_memf, p_mem_h, p_mem_l, Cx, 0, nullptr, nullptr, 0, 1, 0, 1);
    launch_gemm(1, Lx, Cx, NKMAX, p_lgc_h, nullptr, NKMAX, (long long)Lx*NKMAX,
                p_vcT_h, nullptr, NKMAX, (long long)Cx*NKMAX,
                p_memf, p_mem_h, p_mem_l, Cx, (long long)Lx*Cx, nullptr, nullptr, 1, 0, 1, Bx);

    // -------- heads --------
    // t1 = mem @ [kW1|vW1] + [kb1|vb1]   (N=128 merged)
    launch_gemm(3, NROW, 2*MRx, Cx, p_mem_h, p_mem_l, Cx, 0, p_w1T_h, p_w1T_l, Cx, 0,
                p_memf, p_t1_h, p_t1_l, 2*MRx, 0, p_bias1, nullptr, 0, 0, 1, 1);
    float* outk = (float*)d_out;
    float* outv = (float*)d_out + (size_t)NROW * Cx;
    launch_gemm(3, NROW, Cx, MRx, p_t1_h, p_t1_l, 2*MRx, 0, p_kW2T_h, p_kW2T_l, MRx, 0,
                outk, p_mem_h, p_mem_l, Cx, 0, kb2, p_scal + 1, 0, 1, 0, 1);
    launch_gemm(3, NROW, Cx, MRx, p_t1_h + MRx, p_t1_l + MRx, 2*MRx, 0, p_vW2T_h, p_vW2T_l, MRx, 0,
                outv, p_mem_h, p_mem_l, Cx, 0, vb2, p_scal + 2, 0, 1, 0, 1);

    tail_kernel<<<1, 256>>>((float*)d_out, 2 * NROW * Cx, out_size);
}

// round 5
// speedup vs baseline: 7.5558x; 1.6740x over previous
#include <cuda_runtime.h>
#include <math.h>

// ---------------- problem constants ----------------
static constexpr int Bx = 32, Lx = 680, Cx = 1024;
static constexpr int Sx = 10, SLOTSx = 32, Rx = 8, NCATx = 22;
static constexpr int MRx = 64, AHx = 128;
static constexpr int NROW = Bx * Lx;            // 21760
static constexpr int NKMAX = Sx * SLOTSx;       // 320
static constexpr int NQ = NROW * Cx;            // 22282240

__constant__ int c_begin[10] = {0,1,5,14,30,55,91,155,255,424};

// ---------------- device scratch ----------------
__device__ unsigned g_x_h[NQ];
__device__ unsigned g_qs_h[NQ];
__device__ unsigned g_WqT_h[Cx*Cx], g_WqT_l[Cx*Cx];
__device__ unsigned g_WkT_h[Cx*Cx], g_WkT_l[Cx*Cx];
__device__ unsigned g_WvT_h[Cx*Cx], g_WvT_l[Cx*Cx];
__device__ unsigned g_aW1T_h[AHx*Cx], g_aW1T_l[AHx*Cx];
__device__ unsigned g_w1T_h[(2*MRx)*Cx], g_w1T_l[(2*MRx)*Cx];
__device__ unsigned g_kW2T_h[Cx*MRx], g_kW2T_l[Cx*MRx];
__device__ unsigned g_vW2T_h[Cx*MRx], g_vW2T_l[Cx*MRx];
__device__ unsigned g_shm_h[NKMAX*Cx];
__device__ unsigned g_cB_h[2560*Cx];

__device__ float    g_skf[NKMAX*Cx];
__device__ unsigned g_sk_h[NKMAX*Cx];
__device__ float    g_svTf[Cx*NKMAX];
__device__ unsigned g_svT_h[Cx*NKMAX];
__device__ float    g_cbkf[2560*Cx];
__device__ float    g_cbvTf[Cx*2560];
__device__ unsigned g_kc_h[Bx*NKMAX*Cx];
__device__ unsigned g_vcT_h[Bx*Cx*NKMAX];
__device__ float    g_lgsf[NROW*NKMAX], g_lgcf[NROW*NKMAX];
__device__ unsigned g_lgs_h[NROW*NKMAX], g_lgc_h[NROW*NKMAX];
__device__ float    g_qhf[NROW*AHx];
__device__ float    g_memf[NQ];
__device__ unsigned g_mem_h[NQ], g_mem_l[NQ];
__device__ unsigned g_t1_h[NROW*(2*MRx)], g_t1_l[NROW*(2*MRx)];
__device__ float    g_acat[NCATx*AHx];
__device__ float    g_ascale[Sx*AHx];
__device__ float    g_alpha[NROW];
__device__ float    g_scal[4];
__device__ float    g_bias1[2*MRx];

// ---------------- helpers ----------------
__device__ __forceinline__ void split_tf32(float x, unsigned& hi, unsigned& lo) {
    unsigned h; asm("cvt.rna.tf32.f32 %0, %1;" : "=r"(h) : "f"(x));
    float hf = __uint_as_float(h);
    unsigned l; asm("cvt.rna.tf32.f32 %0, %1;" : "=r"(l) : "f"(x - hf));
    hi = h; lo = l;
}
__device__ __forceinline__ unsigned to_tf32(float x) {
    unsigned h; asm("cvt.rna.tf32.f32 %0, %1;" : "=r"(h) : "f"(x)); return h;
}
__device__ __forceinline__ void mma8(float* d, const unsigned* a, const unsigned* b) {
    asm volatile(
        "mma.sync.aligned.m16n8k8.row.col.f32.tf32.tf32.f32 "
        "{%0,%1,%2,%3}, {%4,%5,%6,%7}, {%8,%9}, {%0,%1,%2,%3};"
        : "+f"(d[0]), "+f"(d[1]), "+f"(d[2]), "+f"(d[3])
        : "r"(a[0]), "r"(a[1]), "r"(a[2]), "r"(a[3]), "r"(b[0]), "r"(b[1]));
}
__device__ __forceinline__ uint4 ldsm4(unsigned a) {
    uint4 r;
    asm volatile("ldmatrix.sync.aligned.m8n8.x4.shared.b16 {%0,%1,%2,%3}, [%4];"
        : "=r"(r.x), "=r"(r.y), "=r"(r.z), "=r"(r.w) : "r"(a));
    return r;
}
__device__ __forceinline__ unsigned smaddr(const void* p) {
    unsigned a;
    asm("{.reg .u64 u; cvta.to.shared.u64 u, %1; cvt.u32.u64 %0, u;}" : "=r"(a) : "l"(p));
    return a;
}
__device__ __forceinline__ void cp16(unsigned dst, const void* src, bool ok) {
    int sz = ok ? 16 : 0;
    asm volatile("cp.async.cg.shared.global [%0], [%1], 16, %2;\n" :: "r"(dst), "l"(src), "r"(sz));
}
__device__ __forceinline__ void cp_commit() { asm volatile("cp.async.commit_group;"); }
template<int N> __device__ __forceinline__ void cp_wait() {
    asm volatile("cp.async.wait_group %0;" :: "n"(N));
}

// ---------------- prep ----------------
__global__ void prep_kernel(const float* gk, const float* gv, const float* lt) {
    float temp = expf(lt[0]);
    temp = fminf(fmaxf(temp, 0.05f), 1.0f);
    g_scal[0] = (1.0f / 32.0f) / temp;
    g_scal[1] = 1.0f / (1.0f + expf(-gk[0]));
    g_scal[2] = 1.0f / (1.0f + expf(-gv[0]));
}

// ---------------- fp32 -> tf32 hi plane ----------------
__global__ void cvt_kernel(const float* __restrict__ in, unsigned* __restrict__ hi, int n4) {
    int i = blockIdx.x * 256 + threadIdx.x;
    if (i >= n4) return;
    float4 v = ((const float4*)in)[i];
    uint4 h;
    h.x = to_tf32(v.x); h.y = to_tf32(v.y); h.z = to_tf32(v.z); h.w = to_tf32(v.w);
    ((uint4*)hi)[i] = h;
}

// ---------------- transpose + split: in [R][C] -> planes [C][R] ----------------
__global__ void tsplit_kernel(const float* __restrict__ in, int R, int C,
                              unsigned* __restrict__ oh, unsigned* __restrict__ ol)
{
    __shared__ float t[32][33];
    int r0 = blockIdx.y * 32, c0 = blockIdx.x * 32;
    int tx = threadIdx.x, ty = threadIdx.y;
    #pragma unroll
    for (int i = 0; i < 32; i += 8) {
        int r = r0 + ty + i;
        t[ty + i][tx] = (r < R && c0 + tx < C) ? in[(size_t)r * C + c0 + tx] : 0.f;
    }
    __syncthreads();
    #pragma unroll
    for (int i = 0; i < 32; i += 8) {
        int c = c0 + ty + i, r = r0 + tx;
        if (c < C && r < R) {
            unsigned h, l; split_tf32(t[tx][ty + i], h, l);
            oh[(size_t)c * R + r] = h;
            ol[(size_t)c * R + r] = l;
        }
    }
}

// ---------------- GEMM ----------------
static constexpr int WR_F32 = 1, WR_SPLIT = 2, WR_HI = 4;

struct GemmArgs {
    int M, N, K;
    const unsigned *Ah, *Al; int lda; long long sA;
    const unsigned *Bh, *Bl; int ldb; long long sB;   // B is [N][K] (NT)
    float* Cf; unsigned *Chi, *Clo; int ldc; long long sC;
    const float* bias; const float* gate;
    int accum, wr;
};

template<int NPASS>
__global__ void __launch_bounds__(256, 2) gemm_tmpl(GemmArgs g)
{
    constexpr int AW  = 20;
    constexpr int ASZ = 128 * AW;               // 2560 words per plane tile
    constexpr int NPL = (NPASS == 3) ? 2 : 1;
    constexpr int NSTG = (NPASS == 3) ? 2 : 3;
    constexpr int STG = NPL * 2 * ASZ;          // words per stage
    extern __shared__ unsigned sm[];

    const int tid = threadIdx.x, lane = tid & 31, wid = tid >> 5;
    const int wm = wid >> 2, wn = wid & 3, tg = lane & 3, gid = lane >> 2;
    const int bm = blockIdx.y * 128, bn = blockIdx.x * 128;
    const long long z = blockIdx.z;

    const unsigned* Ap[2];
    Ap[0] = g.Ah + z * g.sA;
    Ap[1] = (NPASS == 3) ? g.Al + z * g.sA : Ap[0];
    const unsigned* Bp[2];
    Bp[0] = g.Bh + z * g.sB;
    Bp[1] = (NPASS == 3) ? g.Bl + z * g.sB : Bp[0];

    const unsigned smbase = smaddr(sm);

    const int am = lane >> 3;
    const int a_row = (am & 1) * 8 + (lane & 7);
    const int a_kw  = (am >> 1) * 4;
    const int b_row = (am >> 1) * 8 + (lane & 7);
    const int b_kw  = (am & 1) * 4;
    unsigned aA[4], bA[2];
    #pragma unroll
    for (int mt = 0; mt < 4; mt++)
        aA[mt] = smbase + (unsigned)((wm*64 + mt*16 + a_row) * AW + a_kw) * 4u;
    #pragma unroll
    for (int pr = 0; pr < 2; pr++)
        bA[pr] = smbase + (unsigned)(NPL * ASZ) * 4u
               + (unsigned)((wn*32 + pr*16 + b_row) * AW + b_kw) * 4u;

    float acc[4][4][4];
    #pragma unroll
    for (int mt = 0; mt < 4; mt++)
        #pragma unroll
        for (int nt = 0; nt < 4; nt++)
            #pragma unroll
            for (int u = 0; u < 4; u++) acc[mt][nt][u] = 0.f;

    auto load_stage = [&](int s, int k0) {
        unsigned base = smbase + (unsigned)(s * STG) * 4u;
        #pragma unroll
        for (int i = 0; i < 2 * NPL; i++) {
            int c = tid + i * 256;
            int p = c >> 9, rem = c & 511;
            int row = rem >> 2, kc = (rem & 3) * 4;
            bool ok = (bm + row) < g.M;
            const unsigned* src = ok ? Ap[p] + (size_t)(bm + row) * g.lda + k0 + kc : Ap[p];
            cp16(base + (unsigned)(p * ASZ + row * AW + kc) * 4u, src, ok);
        }
        unsigned bbase = base + (unsigned)(NPL * ASZ) * 4u;
        #pragma unroll
        for (int i = 0; i < 2 * NPL; i++) {
            int c = tid + i * 256;
            int p = c >> 9, rem = c & 511;
            int row = rem >> 2, kc = (rem & 3) * 4;
            bool ok = (bn + row) < g.N;
            const unsigned* src = ok ? Bp[p] + (size_t)(bn + row) * g.ldb + k0 + kc : Bp[p];
            cp16(bbase + (unsigned)(p * ASZ + row * AW + kc) * 4u, src, ok);
        }
    };

    auto compute = [&](int s) {
        const unsigned so = (unsigned)(s * STG) * 4u;
        #pragma unroll
        for (int kk = 0; kk < 16; kk += 8) {
            const unsigned kb = so + (unsigned)kk * 4u;
            unsigned bh[4][2], bl[4][2];
            #pragma unroll
            for (int pr = 0; pr < 2; pr++) {
                uint4 r = ldsm4(bA[pr] + kb);
                bh[pr*2+0][0] = r.x; bh[pr*2+0][1] = r.y;
                bh[pr*2+1][0] = r.z; bh[pr*2+1][1] = r.w;
                if (NPASS == 3) {
                    uint4 q = ldsm4(bA[pr] + kb + (unsigned)ASZ * 4u);
                    bl[pr*2+0][0] = q.x; bl[pr*2+0][1] = q.y;
                    bl[pr*2+1][0] = q.z; bl[pr*2+1][1] = q.w;
                }
            }
            #pragma unroll
            for (int mt = 0; mt < 4; mt++) {
                uint4 ah4 = ldsm4(aA[mt] + kb);
                uint4 al4 = make_uint4(0,0,0,0);
                if (NPASS == 3) al4 = ldsm4(aA[mt] + kb + (unsigned)ASZ * 4u);
                #pragma unroll
                for (int nt = 0; nt < 4; nt++) {
                    mma8(acc[mt][nt], (const unsigned*)&ah4, bh[nt]);
                    if (NPASS == 3) {
                        mma8(acc[mt][nt], (const unsigned*)&ah4, bl[nt]);
                        mma8(acc[mt][nt], (const unsigned*)&al4, bh[nt]);
                    }
                }
            }
        }
    };

    const int nK = g.K >> 4;
    if (NSTG == 3) {
        load_stage(0, 0);
        cp_commit();
        if (nK > 1) load_stage(1, 16);
        cp_commit();
        for (int kt = 0; kt < nK; kt++) {
            cp_wait<1>();
            __syncthreads();
            if (kt + 2 < nK) load_stage((kt + 2) % 3, (kt + 2) << 4);
            cp_commit();
            compute(kt % 3);
        }
    } else {
        load_stage(0, 0);
        cp_commit();
        for (int kt = 0; kt < nK; kt++) {
            if (kt + 1 < nK) {
                load_stage((kt + 1) & 1, (kt + 1) << 4);
                cp_commit();
                cp_wait<1>();
            } else {
                cp_wait<0>();
            }
            __syncthreads();
            compute(kt & 1);
            __syncthreads();
        }
    }

    // ---------------- epilogue ----------------
    const float gt = g.gate ? *g.gate : 1.0f;
    float* Cf = g.Cf + z * g.sC;
    unsigned* Chi = g.Chi + z * g.sC;
    unsigned* Clo = g.Clo + z * g.sC;
    #pragma unroll
    for (int mt = 0; mt < 4; mt++) {
        int r0 = bm + wm * 64 + mt * 16 + gid;
        int r1 = r0 + 8;
        #pragma unroll
        for (int nt = 0; nt < 4; nt++) {
            int col = bn + wn * 32 + nt * 8 + 2 * tg;
            if (col >= g.N) continue;
            float b0 = g.bias ? g.bias[col]     : 0.f;
            float b1 = g.bias ? g.bias[col + 1] : 0.f;
            #pragma unroll
            for (int half = 0; half < 2; half++) {
                int r = half ? r1 : r0;
                if (r >= g.M) continue;
                size_t o = (size_t)r * g.ldc + col;
                float v0 = gt * (acc[mt][nt][half*2+0] + b0);
                float v1 = gt * (acc[mt][nt][half*2+1] + b1);
                if (g.accum) { v0 += Cf[o]; v1 += Cf[o+1]; }
                if (g.wr & WR_F32) *(float2*)(Cf + o) = make_float2(v0, v1);
                if (g.wr & WR_SPLIT) {
                    unsigned h0,l0,h1,l1;
                    split_tf32(v0, h0, l0); split_tf32(v1, h1, l1);
                    Chi[o] = h0; Chi[o+1] = h1;
                    Clo[o] = l0; Clo[o+1] = l1;
                }
                if (g.wr & WR_HI) {
                    Chi[o] = to_tf32(v0); Chi[o+1] = to_tf32(v1);
                }
            }
        }
    }
}

// ---------------- kc (hi plane): kc = sk + sum_r a_r * cbk_r ----------------
__global__ void __launch_bounds__(256) kcvc_k_kernel(const int* __restrict__ catids,
                                                     const float* __restrict__ cat_A)
{
    int blk = blockIdx.x;            // b*320 + key
    int b = blk / 320, key = blk % 320;
    int v = key >> 5;
    int cid = catids[b]; if (cid < 0) cid = 0;
    float a[Rx];
    #pragma unroll
    for (int r = 0; r < Rx; r++) a[r] = cat_A[(cid*Sx + v)*Rx + r];
    int c = threadIdx.x * 4;
    float4 ka = *(const float4*)(g_skf + (size_t)key*Cx + c);
    #pragma unroll
    for (int r = 0; r < Rx; r++) {
        int s = key & 31;
        size_t idx = ((size_t)((v*Rx + r)*SLOTSx + s))*Cx + c;
        float4 kb = *(const float4*)(g_cbkf + idx);
        ka.x += a[r]*kb.x; ka.y += a[r]*kb.y; ka.z += a[r]*kb.z; ka.w += a[r]*kb.w;
    }
    size_t o = ((size_t)(b*320 + key))*Cx + c;
    uint4 h;
    h.x = to_tf32(ka.x); h.y = to_tf32(ka.y); h.z = to_tf32(ka.z); h.w = to_tf32(ka.w);
    *(uint4*)(g_kc_h + o) = h;
}

// ---------------- vcT (hi plane): vcT[b][c][key] = svT[c][key] + sum_r a * cbvT ----------------
__global__ void __launch_bounds__(320) kcvc_v_kernel(const int* __restrict__ catids,
                                                     const float* __restrict__ cat_A)
{
    int c = blockIdx.x;        // 0..1023
    int b = blockIdx.y;        // 0..31
    int key = threadIdx.x;     // 0..319
    int cid = catids[b]; if (cid < 0) cid = 0;
    int v = key >> 5, s = key & 31;
    const float* ar = cat_A + (cid*Sx + v)*Rx;
    float acc = g_svTf[(size_t)c*NKMAX + key];
    #pragma unroll
    for (int r = 0; r < Rx; r++)
        acc += ar[r] * g_cbvTf[(size_t)c*2560 + (v*Rx + r)*SLOTSx + s];
    g_vcT_h[((size_t)b*Cx + c)*NKMAX + key] = to_tf32(acc);
}

// ---------------- alpha constant tables ----------------
__global__ void aconst_kernel(const float* __restrict__ cat_emb,
                              const float* __restrict__ scale_emb,
                              const float* __restrict__ aW1,
                              const float* __restrict__ ab1)
{
    int idx = blockIdx.x;
    int h = threadIdx.x;
    if (idx < NCATx) {
        float acc = 0.f;
        const float* ce = cat_emb + (size_t)idx * Cx;
        for (int c = 0; c < Cx; c++)
            acc += ce[c] * aW1[(size_t)(Cx + c)*AHx + h];
        g_acat[idx*AHx + h] = acc;
    } else {
        int i = idx - NCATx;
        float acc = ab1[h];
        const float* se = scale_emb + (size_t)i * Cx;
        for (int c = 0; c < Cx; c++)
            acc += se[c] * aW1[(size_t)(2*Cx + c)*AHx + h];
        g_ascale[i*AHx + h] = acc;
    }
}

// ---------------- alpha gate per row ----------------
__global__ void __launch_bounds__(256) alpha_kernel(const int* __restrict__ catids,
                                                    const float* __restrict__ aW2,
                                                    const float* __restrict__ ab2)
{
    int w = threadIdx.x >> 5, lane = threadIdx.x & 31;
    int row = blockIdx.x * 8 + w;
    if (row >= NROW) return;
    int b = row / Lx, l = row % Lx;
    int cid = catids[b];
    if (cid < 0) { if (lane == 0) g_alpha[row] = 0.f; return; }
    int i = 0;
    #pragma unroll
    for (int u = 1; u < 10; u++) if (l >= c_begin[u]) i = u;
    const float* qhp = g_qhf + (size_t)row*AHx;
    const float* ac  = g_acat + cid*AHx;
    const float* as  = g_ascale + i*AHx;
    float acc = 0.f;
    #pragma unroll
    for (int h = lane; h < AHx; h += 32) {
        float xv = qhp[h] + ac[h] + as[h];
        float ge = 0.5f*xv*(1.0f + erff(xv*0.70710678118654752f));
        acc += ge * aW2[h];
    }
    #pragma unroll
    for (int o = 16; o > 0; o >>= 1) acc += __shfl_xor_sync(0xffffffffu, acc, o);
    if (lane == 0) g_alpha[row] = 1.0f/(1.0f + expf(-(acc + ab2[0])));
}

// ---------------- masked softmax + alpha prescale -> tf32 hi planes ----------------
__global__ void __launch_bounds__(256) softmax_kernel()
{
    int w = threadIdx.x >> 5, lane = threadIdx.x & 31;
    int row = blockIdx.x * 8 + w;
    if (row >= NROW) return;
    int l = row % Lx;
    int i = 0;
    #pragma unroll
    for (int u = 1; u < 10; u++) if (l >= c_begin[u]) i = u;
    int nk = (i + 1) * SLOTSx;
    float ls = g_scal[0];
    float a = g_alpha[row];
    #pragma unroll
    for (int s = 0; s < 2; s++) {
        const float* p = (s ? g_lgcf : g_lgsf) + (size_t)row * NKMAX;
        unsigned* q = (s ? g_lgc_h : g_lgs_h) + (size_t)row * NKMAX;
        float wgt = s ? a : (1.0f - a);
        float v[10];
        int cnt = 0;
        float mx = -3.4e38f;
        for (int j = lane; j < nk; j += 32) { float t = p[j]*ls; v[cnt++] = t; mx = fmaxf(mx, t); }
        #pragma unroll
        for (int o = 16; o > 0; o >>= 1) mx = fmaxf(mx, __shfl_xor_sync(0xffffffffu, mx, o));
        float sum = 0.f;
        for (int c2 = 0; c2 < cnt; c2++) { v[c2] = expf(v[c2] - mx); sum += v[c2]; }
        #pragma unroll
        for (int o = 16; o > 0; o >>= 1) sum += __shfl_xor_sync(0xffffffffu, sum, o);
        float inv = wgt / sum;
        cnt = 0;
        for (int j = lane; j < NKMAX; j += 32)
            q[j] = (j < nk) ? to_tf32(v[cnt++] * inv) : 0u;
    }
}

// ---------------- tail ----------------
__global__ void tail_kernel(float* out, int n2, int total) {
    int idx = n2 + blockIdx.x*blockDim.x + threadIdx.x;
    if (idx < total) out[idx] = 0.f;
}

// ---------------- host helpers ----------------
static void launch_gemm(int npass, int M, int N, int K,
                        const unsigned* Ah, const unsigned* Al, int lda, long long sA,
                        const unsigned* Bh, const unsigned* Bl, int ldb, long long sB,
                        float* Cf, unsigned* Chi, unsigned* Clo, int ldc, long long sC,
                        const float* bias, const float* gate,
                        int accum, int wr, int batches)
{
    GemmArgs g;
    g.M=M; g.N=N; g.K=K;
    g.Ah=Ah; g.Al=Al; g.lda=lda; g.sA=sA;
    g.Bh=Bh; g.Bl=Bl; g.ldb=ldb; g.sB=sB;
    g.Cf=Cf; g.Chi=Chi; g.Clo=Clo; g.ldc=ldc; g.sC=sC;
    g.bias=bias; g.gate=gate; g.accum=accum; g.wr=wr;
    dim3 grid((N + 127)/128, (M + 127)/128, batches);
    if (npass == 3) gemm_tmpl<3><<<grid, 256, 81920>>>(g);
    else            gemm_tmpl<1><<<grid, 256, 61440>>>(g);
}

static void launch_tsplit(const float* in, int R, int C, unsigned* oh, unsigned* ol)
{
    dim3 grid((C + 31)/32, (R + 31)/32);
    tsplit_kernel<<<grid, dim3(32, 8)>>>(in, R, C, oh, ol);
}

// ---------------- launch ----------------
extern "C" void kernel_launch(void* const* d_in, const int* in_sizes, int n_in,
                              void* d_out, int out_size) {
    const float* x        = (const float*)d_in[0];
    const int*   catids   = (const int*)  d_in[1];
    const float* shmem    = (const float*)d_in[2];
    const float* cat_A    = (const float*)d_in[3];
    const float* cat_B    = (const float*)d_in[4];
    const float* cat_emb  = (const float*)d_in[5];
    const float* scale_emb= (const float*)d_in[6];
    const float* Wq       = (const float*)d_in[7];
    const float* Wk       = (const float*)d_in[8];
    const float* Wv       = (const float*)d_in[9];
    const float* aW1      = (const float*)d_in[10];
    const float* ab1      = (const float*)d_in[11];
    const float* aW2      = (const float*)d_in[12];
    const float* ab2      = (const float*)d_in[13];
    const float* kW1      = (const float*)d_in[14];
    const float* kb1      = (const float*)d_in[15];
    const float* kW2      = (const float*)d_in[16];
    const float* kb2      = (const float*)d_in[17];
    const float* vW1      = (const float*)d_in[18];
    const float* vb1      = (const float*)d_in[19];
    const float* vW2      = (const float*)d_in[20];
    const float* vb2      = (const float*)d_in[21];
    const float* gk       = (const float*)d_in[22];
    const float* gv       = (const float*)d_in[23];
    const float* lt       = (const float*)d_in[24];

    cudaFuncSetAttribute(gemm_tmpl<3>, cudaFuncAttributeMaxDynamicSharedMemorySize, 81920);
    cudaFuncSetAttribute(gemm_tmpl<1>, cudaFuncAttributeMaxDynamicSharedMemorySize, 61440);

    #define SYM(t, p, s) t p; cudaGetSymbolAddress((void**)&p, s)
    SYM(unsigned*, p_x_h, g_x_h);
    SYM(unsigned*, p_qs_h, g_qs_h);
    SYM(unsigned*, p_WqT_h, g_WqT_h); SYM(unsigned*, p_WqT_l, g_WqT_l);
    SYM(unsigned*, p_WkT_h, g_WkT_h); SYM(unsigned*, p_WkT_l, g_WkT_l);
    SYM(unsigned*, p_WvT_h, g_WvT_h); SYM(unsigned*, p_WvT_l, g_WvT_l);
    SYM(unsigned*, p_aW1T_h, g_aW1T_h); SYM(unsigned*, p_aW1T_l, g_aW1T_l);
    SYM(unsigned*, p_w1T_h, g_w1T_h); SYM(unsigned*, p_w1T_l, g_w1T_l);
    SYM(unsigned*, p_kW2T_h, g_kW2T_h); SYM(unsigned*, p_kW2T_l, g_kW2T_l);
    SYM(unsigned*, p_vW2T_h, g_vW2T_h); SYM(unsigned*, p_vW2T_l, g_vW2T_l);
    SYM(unsigned*, p_shm_h, g_shm_h);
    SYM(unsigned*, p_cB_h, g_cB_h);
    SYM(float*,    p_skf, g_skf);
    SYM(unsigned*, p_sk_h, g_sk_h);
    SYM(float*,    p_svTf, g_svTf);
    SYM(unsigned*, p_svT_h, g_svT_h);
    SYM(float*,    p_cbkf, g_cbkf);
    SYM(float*,    p_cbvTf, g_cbvTf);
    SYM(unsigned*, p_kc_h, g_kc_h);
    SYM(unsigned*, p_vcT_h, g_vcT_h);
    SYM(float*,    p_lgsf, g_lgsf);   SYM(float*,    p_lgcf, g_lgcf);
    SYM(unsigned*, p_lgs_h, g_lgs_h); SYM(unsigned*, p_lgc_h, g_lgc_h);
    SYM(float*,    p_qhf, g_qhf);
    SYM(float*,    p_memf, g_memf);
    SYM(unsigned*, p_mem_h, g_mem_h); SYM(unsigned*, p_mem_l, g_mem_l);
    SYM(unsigned*, p_t1_h, g_t1_h);   SYM(unsigned*, p_t1_l, g_t1_l);
    SYM(float*,    p_scal, g_scal);
    SYM(float*,    p_bias1, g_bias1);
    #undef SYM

    prep_kernel<<<1, 1>>>(gk, gv, lt);

    // -------- operand preparation --------
    cvt_kernel<<<(NQ/4 + 255)/256, 256>>>(x, p_x_h, NQ/4);
    cvt_kernel<<<(NKMAX*Cx/4 + 255)/256, 256>>>(shmem, p_shm_h, NKMAX*Cx/4);
    cvt_kernel<<<(2560*Cx/4 + 255)/256, 256>>>(cat_B, p_cB_h, 2560*Cx/4);
    launch_tsplit(Wq, Cx, Cx, p_WqT_h, p_WqT_l);
    launch_tsplit(Wk, Cx, Cx, p_WkT_h, p_WkT_l);
    launch_tsplit(Wv, Cx, Cx, p_WvT_h, p_WvT_l);
    launch_tsplit(aW1, Cx, AHx, p_aW1T_h, p_aW1T_l);
    launch_tsplit(kW1, Cx, MRx, p_w1T_h, p_w1T_l);
    launch_tsplit(vW1, Cx, MRx, p_w1T_h + MRx*Cx, p_w1T_l + MRx*Cx);
    launch_tsplit(kW2, MRx, Cx, p_kW2T_h, p_kW2T_l);
    launch_tsplit(vW2, MRx, Cx, p_vW2T_h, p_vW2T_l);
    cudaMemcpyAsync(p_bias1, kb1, MRx*sizeof(float), cudaMemcpyDeviceToDevice);
    cudaMemcpyAsync(p_bias1 + MRx, vb1, MRx*sizeof(float), cudaMemcpyDeviceToDevice);

    // -------- projections (all 1-pass) --------
    // query = x @ Wq -> hi plane
    launch_gemm(1, NROW, Cx, Cx, p_x_h, nullptr, Cx, 0, p_WqT_h, nullptr, Cx, 0,
                p_memf, p_qs_h, nullptr, Cx, 0, nullptr, nullptr, 0, WR_HI, 1);
    // sk = shmem @ Wk -> f32 + hi
    launch_gemm(1, NKMAX, Cx, Cx, p_shm_h, nullptr, Cx, 0, p_WkT_h, nullptr, Cx, 0,
                p_skf, p_sk_h, nullptr, Cx, 0, nullptr, nullptr, 0, WR_F32|WR_HI, 1);
    // svT = WvT @ shm^T  ([1024][320]) -> f32 + hi
    launch_gemm(1, Cx, NKMAX, Cx, p_WvT_h, nullptr, Cx, 0, p_shm_h, nullptr, Cx, 0,
                p_svTf, p_svT_h, nullptr, NKMAX, 0, nullptr, nullptr, 0, WR_F32|WR_HI, 1);
    // cbk = cat_B @ Wk -> f32
    launch_gemm(1, 2560, Cx, Cx, p_cB_h, nullptr, Cx, 0, p_WkT_h, nullptr, Cx, 0,
                p_cbkf, p_kc_h, nullptr, Cx, 0, nullptr, nullptr, 0, WR_F32, 1);
    // cbvT = WvT @ cat_B^T ([1024][2560]) -> f32
    launch_gemm(1, Cx, 2560, Cx, p_WvT_h, nullptr, Cx, 0, p_cB_h, nullptr, Cx, 0,
                p_cbvTf, p_kc_h, nullptr, 2560, 0, nullptr, nullptr, 0, WR_F32, 1);
    // qh = query @ aW1[:Cx] -> f32
    launch_gemm(1, NROW, AHx, Cx, p_qs_h, nullptr, Cx, 0, p_aW1T_h, nullptr, Cx, 0,
                p_qhf, p_kc_h, nullptr, AHx, 0, nullptr, nullptr, 0, WR_F32, 1);

    // per-batch kc / vcT hi planes
    kcvc_k_kernel<<<Bx*NKMAX, 256>>>(catids, cat_A);
    kcvc_v_kernel<<<dim3(Cx, Bx), 320>>>(catids, cat_A);

    // alpha constants + per-row alpha
    aconst_kernel<<<NCATx + Sx, AHx>>>(cat_emb, scale_emb, aW1, ab1);
    alpha_kernel<<<(NROW + 7)/8, 256>>>(catids, aW2, ab2);

    // -------- logits (1-pass) --------
    launch_gemm(1, NROW, NKMAX, Cx, p_qs_h, nullptr, Cx, 0, p_sk_h, nullptr, Cx, 0,
                p_lgsf, p_lgs_h, nullptr, NKMAX, 0, nullptr, nullptr, 0, WR_F32, 1);
    launch_gemm(1, Lx, NKMAX, Cx, p_qs_h, nullptr, Cx, (long long)Lx*Cx,
                p_kc_h, nullptr, Cx, (long long)NKMAX*Cx,
                p_lgcf, p_lgs_h, nullptr, NKMAX, (long long)Lx*NKMAX, nullptr, nullptr, 0, WR_F32, Bx);

    // masked softmax -> tf32 hi planes (prescaled by (1-a)/a)
    softmax_kernel<<<(NROW + 7)/8, 256>>>();

    // -------- PV (1-pass) --------
    launch_gemm(1, NROW, Cx, NKMAX, p_lgs_h, nullptr, NKMAX, 0, p_svT_h, nullptr, NKMAX, 0,
                p_memf, p_mem_h, nullptr, Cx, 0, nullptr, nullptr, 0, WR_F32, 1);
    launch_gemm(1, Lx, Cx, NKMAX, p_lgc_h, nullptr, NKMAX, (long long)Lx*NKMAX,
                p_vcT_h, nullptr, NKMAX, (long long)Cx*NKMAX,
                p_memf, p_mem_h, p_mem_l, Cx, (long long)Lx*Cx, nullptr, nullptr, 1, WR_SPLIT, Bx);

    // -------- heads (3-pass) --------
    launch_gemm(3, NROW, 2*MRx, Cx, p_mem_h, p_mem_l, Cx, 0, p_w1T_h, p_w1T_l, Cx, 0,
                p_memf, p_t1_h, p_t1_l, 2*MRx, 0, p_bias1, nullptr, 0, WR_SPLIT, 1);
    float* outk = (float*)d_out;
    float* outv = (float*)d_out + (size_t)NROW * Cx;
    launch_gemm(3, NROW, Cx, MRx, p_t1_h, p_t1_l, 2*MRx, 0, p_kW2T_h, p_kW2T_l, MRx, 0,
                outk, p_mem_h, nullptr, Cx, 0, kb2, p_scal + 1, 0, WR_F32, 1);
    launch_gemm(3, NROW, Cx, MRx, p_t1_h + MRx, p_t1_l + MRx, 2*MRx, 0, p_vW2T_h, p_vW2T_l, MRx, 0,
                outv, p_mem_h, nullptr, Cx, 0, vb2, p_scal + 2, 0, WR_F32, 1);

    tail_kernel<<<1, 256>>>((float*)d_out, 2 * NROW * Cx, out_size);
}